// round 1
// baseline (speedup 1.0000x reference)
#include <cuda_runtime.h>
#include <math.h>

#define DIMC   768
#define HIDDENC 3072
#define SEQ    1024
#define BATCH  16
#define NTOK   (BATCH*SEQ)   // 16384
#define HEADSC 12
#define HDIM   64
#define LN_EPS 1e-5f

// ---------------- scratch (static device arrays; no allocation allowed) ----------------
__device__ float g_h  [NTOK*DIMC];
__device__ float g_q  [NTOK*DIMC];
__device__ float g_k  [NTOK*DIMC];
__device__ float g_v  [NTOK*DIMC];
__device__ float g_ctx[NTOK*DIMC];
__device__ float g_x1 [NTOK*DIMC];
__device__ float g_h2 [NTOK*DIMC];
__device__ float g_ffn[NTOK*HIDDENC];

// ---------------- LayerNorm: one block per row (768 cols, 256 threads) ----------------
__global__ __launch_bounds__(256) void ln_kernel(
    const float* __restrict__ x, const float* __restrict__ g,
    const float* __restrict__ b, float* __restrict__ out)
{
    const int row = blockIdx.x;
    const int t = threadIdx.x;
    const float* xr = x + (size_t)row * DIMC;
    float v0 = xr[t], v1 = xr[t + 256], v2 = xr[t + 512];
    float s  = v0 + v1 + v2;
    float ss = v0*v0 + v1*v1 + v2*v2;
    #pragma unroll
    for (int o = 16; o; o >>= 1) {
        s  += __shfl_xor_sync(0xffffffffu, s,  o);
        ss += __shfl_xor_sync(0xffffffffu, ss, o);
    }
    __shared__ float sm[8], sm2[8];
    const int w = t >> 5, l = t & 31;
    if (l == 0) { sm[w] = s; sm2[w] = ss; }
    __syncthreads();
    if (w == 0) {
        s  = (l < 8) ? sm[l]  : 0.f;
        ss = (l < 8) ? sm2[l] : 0.f;
        #pragma unroll
        for (int o = 4; o; o >>= 1) {
            s  += __shfl_xor_sync(0xffffffffu, s,  o);
            ss += __shfl_xor_sync(0xffffffffu, ss, o);
        }
        if (l == 0) {
            float mu = s * (1.f / DIMC);
            sm[0]  = mu;
            sm2[0] = rsqrtf(ss * (1.f / DIMC) - mu * mu + LN_EPS);
        }
    }
    __syncthreads();
    const float mu = sm[0], rstd = sm2[0];
    float* orow = out + (size_t)row * DIMC;
    orow[t]       = (v0 - mu) * rstd * g[t]       + b[t];
    orow[t + 256] = (v1 - mu) * rstd * g[t + 256] + b[t + 256];
    orow[t + 512] = (v2 - mu) * rstd * g[t + 512] + b[t + 512];
}

// ---------------- SGEMM: C = act(A@B + bias) [+ res]  (128x128x8, 8x8 micro) ----------
// A: [M,K] row-major, B: [K,N] row-major. M%128==0, N%128==0, K%8==0 (all true here).
__global__ __launch_bounds__(256) void sgemm_kernel(
    const float* __restrict__ A, const float* __restrict__ B,
    const float* __restrict__ bias, const float* __restrict__ res,
    float* __restrict__ C, int M, int N, int K, int do_gelu)
{
    __shared__ float As[8][128];
    __shared__ float Bs[8][128];
    const int bx = blockIdx.x * 128;   // col tile
    const int by = blockIdx.y * 128;   // row tile
    const int tid = threadIdx.x;
    const int tx = tid & 15;           // 0..15  (col group of 8)
    const int ty = tid >> 4;           // 0..15  (row group of 8)

    float acc[8][8];
    #pragma unroll
    for (int i = 0; i < 8; i++)
        #pragma unroll
        for (int j = 0; j < 8; j++) acc[i][j] = 0.f;

    const int arow = tid >> 1;         // 0..127
    const int acol = (tid & 1) * 4;    // 0 or 4
    const int brow = tid >> 5;         // 0..7
    const int bcol = (tid & 31) * 4;   // 0..124

    const float* Aptr = A + (size_t)(by + arow) * K + acol;
    const float* Bptr = B + (size_t)brow * N + bx + bcol;

    for (int k0 = 0; k0 < K; k0 += 8) {
        float4 a  = *(const float4*)(Aptr + k0);
        float4 bb = *(const float4*)(Bptr + (size_t)k0 * N);
        As[acol + 0][arow] = a.x;
        As[acol + 1][arow] = a.y;
        As[acol + 2][arow] = a.z;
        As[acol + 3][arow] = a.w;
        *(float4*)&Bs[brow][bcol] = bb;
        __syncthreads();
        #pragma unroll
        for (int k = 0; k < 8; k++) {
            float4 a0 = *(const float4*)&As[k][ty * 8];
            float4 a1 = *(const float4*)&As[k][ty * 8 + 4];
            float4 b0 = *(const float4*)&Bs[k][tx * 8];
            float4 b1 = *(const float4*)&Bs[k][tx * 8 + 4];
            float am[8] = {a0.x, a0.y, a0.z, a0.w, a1.x, a1.y, a1.z, a1.w};
            float bn[8] = {b0.x, b0.y, b0.z, b0.w, b1.x, b1.y, b1.z, b1.w};
            #pragma unroll
            for (int i = 0; i < 8; i++)
                #pragma unroll
                for (int j = 0; j < 8; j++)
                    acc[i][j] += am[i] * bn[j];
        }
        __syncthreads();
    }

    // epilogue: bias (+gelu) (+residual)
    #pragma unroll
    for (int i = 0; i < 8; i++) {
        const int row = by + ty * 8 + i;
        float* crow = C + (size_t)row * N + bx + tx * 8;
        const float* rrow = res ? (res + (size_t)row * N + bx + tx * 8) : nullptr;
        #pragma unroll
        for (int jj = 0; jj < 8; jj += 4) {
            float4 vo;
            float* vp = &vo.x;
            #pragma unroll
            for (int u = 0; u < 4; u++) {
                const int col = bx + tx * 8 + jj + u;
                float t = acc[i][jj + u] + bias[col];
                if (do_gelu) t = 0.5f * t * (1.0f + erff(t * 0.70710678118654752f));
                vp[u] = t;
            }
            if (rrow) {
                float4 r = *(const float4*)(rrow + jj);
                vo.x += r.x; vo.y += r.y; vo.z += r.z; vo.w += r.w;
            }
            *(float4*)(crow + jj) = vo;
        }
    }
}

// ---------------- Flash attention (fp32): 1 block = 64 query rows of one (b,h) --------
// q/k/v layout: [B, N, H*D] row-major; head h occupies cols h*64 .. h*64+63.
__global__ __launch_bounds__(64) void attn_kernel(
    const float* __restrict__ q, const float* __restrict__ k,
    const float* __restrict__ v, float* __restrict__ ctx)
{
    const int qt = blockIdx.x, h = blockIdx.y, b = blockIdx.z;
    const int t = threadIdx.x;
    __shared__ float Ks[64][68];   // pad to kill store conflicts
    __shared__ float Vs[64][68];

    const int qrow = b * SEQ + qt * 64 + t;
    const float* qp = q + (size_t)qrow * DIMC + h * HDIM;
    float qr[64];
    #pragma unroll
    for (int d = 0; d < 64; d += 4) {
        float4 x4 = *(const float4*)(qp + d);
        qr[d] = x4.x; qr[d+1] = x4.y; qr[d+2] = x4.z; qr[d+3] = x4.w;
    }

    float O[64];
    #pragma unroll
    for (int d = 0; d < 64; d++) O[d] = 0.f;
    float m = -1e30f, l = 0.f;

    for (int kt = 0; kt < SEQ; kt += 64) {
        const float* kbase = k + (size_t)(b * SEQ + kt) * DIMC + h * HDIM;
        const float* vbase = v + (size_t)(b * SEQ + kt) * DIMC + h * HDIM;
        // coalesced tile load: 1024 float4s, 64 threads; 16 float4s per row
        #pragma unroll
        for (int it = 0; it < 16; it++) {
            int e4  = it * 64 + t;       // 0..1023
            int row = e4 >> 4;
            int d4  = (e4 & 15) * 4;
            *(float4*)&Ks[row][d4] = *(const float4*)(kbase + (size_t)row * DIMC + d4);
            *(float4*)&Vs[row][d4] = *(const float4*)(vbase + (size_t)row * DIMC + d4);
        }
        __syncthreads();
        for (int j = 0; j < 64; j++) {
            float s0 = 0.f, s1 = 0.f, s2 = 0.f, s3 = 0.f;
            #pragma unroll
            for (int d = 0; d < 64; d += 4) {
                float4 kk = *(const float4*)&Ks[j][d];
                s0 += qr[d]     * kk.x;
                s1 += qr[d + 1] * kk.y;
                s2 += qr[d + 2] * kk.z;
                s3 += qr[d + 3] * kk.w;
            }
            float s = ((s0 + s1) + (s2 + s3)) * 0.125f;  // SCALE = 1/sqrt(64)
            if (s > m) {
                float alpha = __expf(m - s);
                l *= alpha;
                #pragma unroll
                for (int d = 0; d < 64; d++) O[d] *= alpha;
                m = s;
            }
            float p = __expf(s - m);
            l += p;
            #pragma unroll
            for (int d = 0; d < 64; d += 4) {
                float4 vv = *(const float4*)&Vs[j][d];
                O[d]     += p * vv.x;
                O[d + 1] += p * vv.y;
                O[d + 2] += p * vv.z;
                O[d + 3] += p * vv.w;
            }
        }
        __syncthreads();
    }

    const float inv = 1.f / l;
    float* op = ctx + (size_t)qrow * DIMC + h * HDIM;
    #pragma unroll
    for (int d = 0; d < 64; d += 4) {
        float4 o4 = make_float4(O[d] * inv, O[d+1] * inv, O[d+2] * inv, O[d+3] * inv);
        *(float4*)(op + d) = o4;
    }
}

// ---------------- launch ----------------
extern "C" void kernel_launch(void* const* d_in, const int* in_sizes, int n_in,
                              void* d_out, int out_size)
{
    const float* x    = (const float*)d_in[0];
    const float* ln1g = (const float*)d_in[1];
    const float* ln1b = (const float*)d_in[2];
    const float* Wq   = (const float*)d_in[3];
    const float* bq   = (const float*)d_in[4];
    const float* Wk   = (const float*)d_in[5];
    const float* bk   = (const float*)d_in[6];
    const float* Wv   = (const float*)d_in[7];
    const float* bv   = (const float*)d_in[8];
    const float* Wo   = (const float*)d_in[9];
    const float* bo   = (const float*)d_in[10];
    const float* ln2g = (const float*)d_in[11];
    const float* ln2b = (const float*)d_in[12];
    const float* W1   = (const float*)d_in[13];
    const float* b1   = (const float*)d_in[14];
    const float* W2   = (const float*)d_in[15];
    const float* b2   = (const float*)d_in[16];
    float* out = (float*)d_out;

    float *h, *q, *k, *v, *ctx, *x1, *h2, *ffn;
    cudaGetSymbolAddress((void**)&h,   g_h);
    cudaGetSymbolAddress((void**)&q,   g_q);
    cudaGetSymbolAddress((void**)&k,   g_k);
    cudaGetSymbolAddress((void**)&v,   g_v);
    cudaGetSymbolAddress((void**)&ctx, g_ctx);
    cudaGetSymbolAddress((void**)&x1,  g_x1);
    cudaGetSymbolAddress((void**)&h2,  g_h2);
    cudaGetSymbolAddress((void**)&ffn, g_ffn);

    const dim3 blk(256);
    const dim3 gd(DIMC / 128, NTOK / 128);       // 6 x 128
    const dim3 gh(HIDDENC / 128, NTOK / 128);    // 24 x 128

    // 1) LN1
    ln_kernel<<<NTOK, blk>>>(x, ln1g, ln1b, h);
    // 2) QKV projections
    sgemm_kernel<<<gd, blk>>>(h, Wq, bq, nullptr, q, NTOK, DIMC, DIMC, 0);
    sgemm_kernel<<<gd, blk>>>(h, Wk, bk, nullptr, k, NTOK, DIMC, DIMC, 0);
    sgemm_kernel<<<gd, blk>>>(h, Wv, bv, nullptr, v, NTOK, DIMC, DIMC, 0);
    // 3) attention
    attn_kernel<<<dim3(SEQ / 64, HEADSC, BATCH), 64>>>(q, k, v, ctx);
    // 4) x1 = x + ctx@Wo + bo
    sgemm_kernel<<<gd, blk>>>(ctx, Wo, bo, x, x1, NTOK, DIMC, DIMC, 0);
    // 5) LN2
    ln_kernel<<<NTOK, blk>>>(x1, ln2g, ln2b, h2);
    // 6) FFN up + exact GELU
    sgemm_kernel<<<gh, blk>>>(h2, W1, b1, nullptr, ffn, NTOK, HIDDENC, DIMC, 1);
    // 7) out = x1 + ffn@W2 + b2   (only writer of d_out; x1 stable across replays)
    sgemm_kernel<<<gd, blk>>>(ffn, W2, b2, x1, out, NTOK, DIMC, HIDDENC, 0);
}

// round 2
// speedup vs baseline: 2.1315x; 2.1315x over previous
#include <cuda_runtime.h>
#include <math.h>
#include <stdint.h>

#define DIMC   768
#define HIDDENC 3072
#define SEQ    1024
#define BATCH  16
#define NTOK   (BATCH*SEQ)   // 16384
#define HEADSC 12
#define HDIM   64
#define LN_EPS 1e-5f

// ---------------- scratch (static device arrays; no allocation allowed) ----------------
__device__ float g_h  [NTOK*DIMC];
__device__ float g_q  [NTOK*DIMC];
__device__ float g_k  [NTOK*DIMC];
__device__ float g_v  [NTOK*DIMC];
__device__ float g_ctx[NTOK*DIMC];
__device__ float g_x1 [NTOK*DIMC];
__device__ float g_h2 [NTOK*DIMC];
__device__ float g_ffn[NTOK*HIDDENC];

// ---------------- helpers ----------------
__device__ __forceinline__ uint32_t f2tf32(float x) {
    uint32_t r;
    asm("cvt.rna.tf32.f32 %0, %1;" : "=r"(r) : "f"(x));
    return r;
}

__device__ __forceinline__ void mma_m16n8k8(float d[4], const uint32_t a[4], const uint32_t b[2]) {
    asm volatile(
        "mma.sync.aligned.m16n8k8.row.col.f32.tf32.tf32.f32 "
        "{%0,%1,%2,%3}, {%4,%5,%6,%7}, {%8,%9}, {%0,%1,%2,%3};"
        : "+f"(d[0]), "+f"(d[1]), "+f"(d[2]), "+f"(d[3])
        : "r"(a[0]), "r"(a[1]), "r"(a[2]), "r"(a[3]), "r"(b[0]), "r"(b[1]));
}

__device__ __forceinline__ void cp_async16(void* smem, const void* gmem) {
    uint32_t s = (uint32_t)__cvta_generic_to_shared(smem);
    asm volatile("cp.async.cg.shared.global [%0], [%1], 16;" :: "r"(s), "l"(gmem));
}

// ---------------- LayerNorm: one block per row (768 cols, 256 threads) ----------------
__global__ __launch_bounds__(256) void ln_kernel(
    const float* __restrict__ x, const float* __restrict__ g,
    const float* __restrict__ b, float* __restrict__ out)
{
    const int row = blockIdx.x;
    const int t = threadIdx.x;
    const float* xr = x + (size_t)row * DIMC;
    float v0 = xr[t], v1 = xr[t + 256], v2 = xr[t + 512];
    float s  = v0 + v1 + v2;
    float ss = v0*v0 + v1*v1 + v2*v2;
    #pragma unroll
    for (int o = 16; o; o >>= 1) {
        s  += __shfl_xor_sync(0xffffffffu, s,  o);
        ss += __shfl_xor_sync(0xffffffffu, ss, o);
    }
    __shared__ float sm[8], sm2[8];
    const int w = t >> 5, l = t & 31;
    if (l == 0) { sm[w] = s; sm2[w] = ss; }
    __syncthreads();
    if (w == 0) {
        s  = (l < 8) ? sm[l]  : 0.f;
        ss = (l < 8) ? sm2[l] : 0.f;
        #pragma unroll
        for (int o = 4; o; o >>= 1) {
            s  += __shfl_xor_sync(0xffffffffu, s,  o);
            ss += __shfl_xor_sync(0xffffffffu, ss, o);
        }
        if (l == 0) {
            float mu = s * (1.f / DIMC);
            sm[0]  = mu;
            sm2[0] = rsqrtf(ss * (1.f / DIMC) - mu * mu + LN_EPS);
        }
    }
    __syncthreads();
    const float mu = sm[0], rstd = sm2[0];
    float* orow = out + (size_t)row * DIMC;
    orow[t]       = (v0 - mu) * rstd * g[t]       + b[t];
    orow[t + 256] = (v1 - mu) * rstd * g[t + 256] + b[t + 256];
    orow[t + 512] = (v2 - mu) * rstd * g[t + 512] + b[t + 512];
}

// ---------------- TF32 tensor-core GEMM: C = act(A@B + bias) [+ res] ------------------
// A: [M,K] row-major, B: [K,N] row-major. M%128==0, N%128==0, K%16==0 (all true here).
// Block tile 128x128x16, 8 warps (2x4), warp tile 64x32, mma.sync m16n8k8 tf32.
#define AS_STRIDE 20    // 16 k-floats + 4 pad  -> A-fragment LDS conflict-free
#define BS_STRIDE 136   // 128 n-floats + 8 pad -> B-fragment LDS conflict-free

__global__ __launch_bounds__(256, 2) void gemm_tf32(
    const float* __restrict__ A, const float* __restrict__ B,
    const float* __restrict__ bias, const float* __restrict__ res,
    float* __restrict__ C, int M, int N, int K, int do_gelu)
{
    __shared__ alignas(16) float As[2][128 * AS_STRIDE];  // [m][k] layout
    __shared__ alignas(16) float Bs[2][16 * BS_STRIDE];   // [k][n] layout

    const int bx = blockIdx.x * 128;
    const int by = blockIdx.y * 128;
    const int tid = threadIdx.x;
    const int wid = tid >> 5;
    const int lane = tid & 31;
    const int g  = lane >> 2;   // groupID   (0..7)
    const int tg = lane & 3;    // thread-in-group (0..3)

    const int wm = (wid & 1) * 64;   // warp row offset in block tile
    const int wn = (wid >> 1) * 32;  // warp col offset in block tile

    // global->smem load mapping (chunks of float4)
    const int a_row = tid >> 2;            // 0..63  (+64 for second chunk)
    const int a_kq  = (tid & 3) * 4;       // 0,4,8,12
    const int b_k   = tid >> 5;            // 0..7   (+8 for second chunk)
    const int b_n   = (tid & 31) * 4;      // 0..124

    const float* Ag1 = A + (size_t)(by + a_row)      * K + a_kq;
    const float* Ag2 = A + (size_t)(by + a_row + 64) * K + a_kq;
    const float* Bg1 = B + (size_t)b_k       * N + bx + b_n;
    const float* Bg2 = B + (size_t)(b_k + 8) * N + bx + b_n;

    float acc[4][4][4];
    #pragma unroll
    for (int mt = 0; mt < 4; mt++)
        #pragma unroll
        for (int nt = 0; nt < 4; nt++)
            #pragma unroll
            for (int r = 0; r < 4; r++) acc[mt][nt][r] = 0.f;

    const int KT = K / 16;

    // prime stage 0
    {
        cp_async16(&As[0][a_row * AS_STRIDE + a_kq],        Ag1);
        cp_async16(&As[0][(a_row + 64) * AS_STRIDE + a_kq], Ag2);
        cp_async16(&Bs[0][b_k * BS_STRIDE + b_n],           Bg1);
        cp_async16(&Bs[0][(b_k + 8) * BS_STRIDE + b_n],     Bg2);
        asm volatile("cp.async.commit_group;");
    }

    for (int kt = 0; kt < KT; kt++) {
        const int s = kt & 1;
        if (kt + 1 < KT) {
            const int ns = s ^ 1;
            const int k0 = (kt + 1) * 16;
            cp_async16(&As[ns][a_row * AS_STRIDE + a_kq],        Ag1 + k0);
            cp_async16(&As[ns][(a_row + 64) * AS_STRIDE + a_kq], Ag2 + k0);
            cp_async16(&Bs[ns][b_k * BS_STRIDE + b_n],           Bg1 + (size_t)k0 * N);
            cp_async16(&Bs[ns][(b_k + 8) * BS_STRIDE + b_n],     Bg2 + (size_t)k0 * N);
            asm volatile("cp.async.commit_group;");
            asm volatile("cp.async.wait_group 1;");
        } else {
            asm volatile("cp.async.wait_group 0;");
        }
        __syncthreads();

        const float* as = As[s];
        const float* bs = Bs[s];
        #pragma unroll
        for (int kk = 0; kk < 16; kk += 8) {
            uint32_t af[4][4];
            #pragma unroll
            for (int mt = 0; mt < 4; mt++) {
                const int m0 = wm + mt * 16 + g;
                af[mt][0] = f2tf32(as[m0 * AS_STRIDE + kk + tg]);
                af[mt][1] = f2tf32(as[(m0 + 8) * AS_STRIDE + kk + tg]);
                af[mt][2] = f2tf32(as[m0 * AS_STRIDE + kk + tg + 4]);
                af[mt][3] = f2tf32(as[(m0 + 8) * AS_STRIDE + kk + tg + 4]);
            }
            uint32_t bf[4][2];
            #pragma unroll
            for (int nt = 0; nt < 4; nt++) {
                const int n0 = wn + nt * 8 + g;
                bf[nt][0] = f2tf32(bs[(kk + tg) * BS_STRIDE + n0]);
                bf[nt][1] = f2tf32(bs[(kk + tg + 4) * BS_STRIDE + n0]);
            }
            #pragma unroll
            for (int mt = 0; mt < 4; mt++)
                #pragma unroll
                for (int nt = 0; nt < 4; nt++)
                    mma_m16n8k8(acc[mt][nt], af[mt], bf[nt]);
        }
        __syncthreads();
    }

    // epilogue: bias (+gelu) (+residual)
    #pragma unroll
    for (int mt = 0; mt < 4; mt++) {
        const int r0 = by + wm + mt * 16 + g;
        #pragma unroll
        for (int nt = 0; nt < 4; nt++) {
            const int c0 = bx + wn + nt * 8 + tg * 2;
            const float b0 = bias[c0], b1 = bias[c0 + 1];
            float v00 = acc[mt][nt][0] + b0;
            float v01 = acc[mt][nt][1] + b1;
            float v10 = acc[mt][nt][2] + b0;
            float v11 = acc[mt][nt][3] + b1;
            if (do_gelu) {
                v00 = 0.5f * v00 * (1.0f + erff(v00 * 0.70710678118654752f));
                v01 = 0.5f * v01 * (1.0f + erff(v01 * 0.70710678118654752f));
                v10 = 0.5f * v10 * (1.0f + erff(v10 * 0.70710678118654752f));
                v11 = 0.5f * v11 * (1.0f + erff(v11 * 0.70710678118654752f));
            }
            if (res) {
                const float2 r01 = *(const float2*)&res[(size_t)r0 * N + c0];
                const float2 r11 = *(const float2*)&res[(size_t)(r0 + 8) * N + c0];
                v00 += r01.x; v01 += r01.y;
                v10 += r11.x; v11 += r11.y;
            }
            *(float2*)&C[(size_t)r0 * N + c0]       = make_float2(v00, v01);
            *(float2*)&C[(size_t)(r0 + 8) * N + c0] = make_float2(v10, v11);
        }
    }
}

// ---------------- Flash attention (fp32): 1 block = 64 query rows of one (b,h) --------
__global__ __launch_bounds__(64) void attn_kernel(
    const float* __restrict__ q, const float* __restrict__ k,
    const float* __restrict__ v, float* __restrict__ ctx)
{
    const int qt = blockIdx.x, h = blockIdx.y, b = blockIdx.z;
    const int t = threadIdx.x;
    __shared__ float Ks[64][68];
    __shared__ float Vs[64][68];

    const int qrow = b * SEQ + qt * 64 + t;
    const float* qp = q + (size_t)qrow * DIMC + h * HDIM;
    float qr[64];
    #pragma unroll
    for (int d = 0; d < 64; d += 4) {
        float4 x4 = *(const float4*)(qp + d);
        qr[d] = x4.x; qr[d+1] = x4.y; qr[d+2] = x4.z; qr[d+3] = x4.w;
    }

    float O[64];
    #pragma unroll
    for (int d = 0; d < 64; d++) O[d] = 0.f;
    float m = -1e30f, l = 0.f;

    for (int kt = 0; kt < SEQ; kt += 64) {
        const float* kbase = k + (size_t)(b * SEQ + kt) * DIMC + h * HDIM;
        const float* vbase = v + (size_t)(b * SEQ + kt) * DIMC + h * HDIM;
        #pragma unroll
        for (int it = 0; it < 16; it++) {
            int e4  = it * 64 + t;
            int row = e4 >> 4;
            int d4  = (e4 & 15) * 4;
            *(float4*)&Ks[row][d4] = *(const float4*)(kbase + (size_t)row * DIMC + d4);
            *(float4*)&Vs[row][d4] = *(const float4*)(vbase + (size_t)row * DIMC + d4);
        }
        __syncthreads();
        for (int j = 0; j < 64; j++) {
            float s0 = 0.f, s1 = 0.f, s2 = 0.f, s3 = 0.f;
            #pragma unroll
            for (int d = 0; d < 64; d += 4) {
                float4 kk = *(const float4*)&Ks[j][d];
                s0 += qr[d]     * kk.x;
                s1 += qr[d + 1] * kk.y;
                s2 += qr[d + 2] * kk.z;
                s3 += qr[d + 3] * kk.w;
            }
            float s = ((s0 + s1) + (s2 + s3)) * 0.125f;
            if (s > m) {
                float alpha = __expf(m - s);
                l *= alpha;
                #pragma unroll
                for (int d = 0; d < 64; d++) O[d] *= alpha;
                m = s;
            }
            float p = __expf(s - m);
            l += p;
            #pragma unroll
            for (int d = 0; d < 64; d += 4) {
                float4 vv = *(const float4*)&Vs[j][d];
                O[d]     += p * vv.x;
                O[d + 1] += p * vv.y;
                O[d + 2] += p * vv.z;
                O[d + 3] += p * vv.w;
            }
        }
        __syncthreads();
    }

    const float inv = 1.f / l;
    float* op = ctx + (size_t)qrow * DIMC + h * HDIM;
    #pragma unroll
    for (int d = 0; d < 64; d += 4) {
        float4 o4 = make_float4(O[d] * inv, O[d+1] * inv, O[d+2] * inv, O[d+3] * inv);
        *(float4*)(op + d) = o4;
    }
}

// ---------------- launch ----------------
extern "C" void kernel_launch(void* const* d_in, const int* in_sizes, int n_in,
                              void* d_out, int out_size)
{
    const float* x    = (const float*)d_in[0];
    const float* ln1g = (const float*)d_in[1];
    const float* ln1b = (const float*)d_in[2];
    const float* Wq   = (const float*)d_in[3];
    const float* bq   = (const float*)d_in[4];
    const float* Wk   = (const float*)d_in[5];
    const float* bk   = (const float*)d_in[6];
    const float* Wv   = (const float*)d_in[7];
    const float* bv   = (const float*)d_in[8];
    const float* Wo   = (const float*)d_in[9];
    const float* bo   = (const float*)d_in[10];
    const float* ln2g = (const float*)d_in[11];
    const float* ln2b = (const float*)d_in[12];
    const float* W1   = (const float*)d_in[13];
    const float* b1   = (const float*)d_in[14];
    const float* W2   = (const float*)d_in[15];
    const float* b2   = (const float*)d_in[16];
    float* out = (float*)d_out;

    float *h, *q, *k, *v, *ctx, *x1, *h2, *ffn;
    cudaGetSymbolAddress((void**)&h,   g_h);
    cudaGetSymbolAddress((void**)&q,   g_q);
    cudaGetSymbolAddress((void**)&k,   g_k);
    cudaGetSymbolAddress((void**)&v,   g_v);
    cudaGetSymbolAddress((void**)&ctx, g_ctx);
    cudaGetSymbolAddress((void**)&x1,  g_x1);
    cudaGetSymbolAddress((void**)&h2,  g_h2);
    cudaGetSymbolAddress((void**)&ffn, g_ffn);

    const dim3 blk(256);
    const dim3 gd(DIMC / 128, NTOK / 128);       // 6 x 128
    const dim3 gh(HIDDENC / 128, NTOK / 128);    // 24 x 128

    // 1) LN1
    ln_kernel<<<NTOK, blk>>>(x, ln1g, ln1b, h);
    // 2) QKV projections (tf32 tensor cores)
    gemm_tf32<<<gd, blk>>>(h, Wq, bq, nullptr, q, NTOK, DIMC, DIMC, 0);
    gemm_tf32<<<gd, blk>>>(h, Wk, bk, nullptr, k, NTOK, DIMC, DIMC, 0);
    gemm_tf32<<<gd, blk>>>(h, Wv, bv, nullptr, v, NTOK, DIMC, DIMC, 0);
    // 3) attention (fp32 flash)
    attn_kernel<<<dim3(SEQ / 64, HEADSC, BATCH), 64>>>(q, k, v, ctx);
    // 4) x1 = x + ctx@Wo + bo
    gemm_tf32<<<gd, blk>>>(ctx, Wo, bo, x, x1, NTOK, DIMC, DIMC, 0);
    // 5) LN2
    ln_kernel<<<NTOK, blk>>>(x1, ln2g, ln2b, h2);
    // 6) FFN up + exact GELU
    gemm_tf32<<<gh, blk>>>(h2, W1, b1, nullptr, ffn, NTOK, HIDDENC, DIMC, 1);
    // 7) out = x1 + ffn@W2 + b2
    gemm_tf32<<<gd, blk>>>(ffn, W2, b2, x1, out, NTOK, DIMC, HIDDENC, 0);
}

// round 4
// speedup vs baseline: 3.8059x; 1.7856x over previous
#include <cuda_runtime.h>
#include <math.h>
#include <stdint.h>

#define DIMC    768
#define HIDDENC 3072
#define SEQ     1024
#define BATCH   16
#define NTOK    (BATCH*SEQ)   // 16384
#define HEADSC  12
#define HDIM    64
#define QKVN    (3*DIMC)      // 2304
#define LN_EPS  1e-5f

// ---------------- scratch (static device arrays; no allocation allowed) ----------------
__device__ float g_h   [NTOK*DIMC];
__device__ float g_qkv [NTOK*QKVN];
__device__ float g_ctx [NTOK*DIMC];
__device__ float g_x1  [NTOK*DIMC];
__device__ float g_h2  [NTOK*DIMC];
__device__ float g_ffn [NTOK*HIDDENC];
// pre-rounded (tf32) weights
__device__ float g_wqkv[DIMC*QKVN];
__device__ float g_bqkv[QKVN];
__device__ float g_wo  [DIMC*DIMC];
__device__ float g_w1  [DIMC*HIDDENC];
__device__ float g_w2  [HIDDENC*DIMC];

// ---------------- helpers ----------------
__device__ __forceinline__ float tf32r(float x) {
    uint32_t u;
    asm("cvt.rna.tf32.f32 %0, %1;" : "=r"(u) : "f"(x));
    return __uint_as_float(u);
}

__device__ __forceinline__ void mma_m16n8k8(float d[4], const uint32_t a[4], const uint32_t b[2]) {
    asm volatile(
        "mma.sync.aligned.m16n8k8.row.col.f32.tf32.tf32.f32 "
        "{%0,%1,%2,%3}, {%4,%5,%6,%7}, {%8,%9}, {%0,%1,%2,%3};"
        : "+f"(d[0]), "+f"(d[1]), "+f"(d[2]), "+f"(d[3])
        : "r"(a[0]), "r"(a[1]), "r"(a[2]), "r"(a[3]), "r"(b[0]), "r"(b[1]));
}

__device__ __forceinline__ void cp_async16(void* smem, const void* gmem) {
    uint32_t s = (uint32_t)__cvta_generic_to_shared(smem);
    asm volatile("cp.async.cg.shared.global [%0], [%1], 16;" :: "r"(s), "l"(gmem));
}

// ---------------- weight prep (per-launch; cheap, graph-capturable) -------------------
__global__ __launch_bounds__(256) void pack_qkv_w(
    const float* __restrict__ Wq, const float* __restrict__ Wk,
    const float* __restrict__ Wv, float* __restrict__ out)
{
    int idx = blockIdx.x * 256 + threadIdx.x;
    if (idx >= DIMC * QKVN) return;
    int k = idx / QKVN, j = idx % QKVN;
    float v = (j < DIMC) ? Wq[k * DIMC + j]
            : (j < 2 * DIMC) ? Wk[k * DIMC + j - DIMC]
            : Wv[k * DIMC + j - 2 * DIMC];
    out[idx] = tf32r(v);
}

__global__ void pack_qkv_b(const float* __restrict__ bq, const float* __restrict__ bk,
                           const float* __restrict__ bv, float* __restrict__ out)
{
    int j = blockIdx.x * 256 + threadIdx.x;
    if (j >= QKVN) return;
    out[j] = (j < DIMC) ? bq[j] : (j < 2 * DIMC) ? bk[j - DIMC] : bv[j - 2 * DIMC];
}

__global__ __launch_bounds__(256) void round_mat(const float* __restrict__ in,
                                                 float* __restrict__ out, int n)
{
    int i = blockIdx.x * 256 + threadIdx.x;
    if (i < n) out[i] = tf32r(in[i]);
}

// ---------------- LayerNorm (tf32-rounded output; feeds GEMM A only) ------------------
__global__ __launch_bounds__(256) void ln_kernel(
    const float* __restrict__ x, const float* __restrict__ g,
    const float* __restrict__ b, float* __restrict__ out)
{
    const int row = blockIdx.x;
    const int t = threadIdx.x;
    const float* xr = x + (size_t)row * DIMC;
    float v0 = xr[t], v1 = xr[t + 256], v2 = xr[t + 512];
    float s  = v0 + v1 + v2;
    float ss = v0*v0 + v1*v1 + v2*v2;
    #pragma unroll
    for (int o = 16; o; o >>= 1) {
        s  += __shfl_xor_sync(0xffffffffu, s,  o);
        ss += __shfl_xor_sync(0xffffffffu, ss, o);
    }
    __shared__ float sm[8], sm2[8];
    const int w = t >> 5, l = t & 31;
    if (l == 0) { sm[w] = s; sm2[w] = ss; }
    __syncthreads();
    if (w == 0) {
        s  = (l < 8) ? sm[l]  : 0.f;
        ss = (l < 8) ? sm2[l] : 0.f;
        #pragma unroll
        for (int o = 4; o; o >>= 1) {
            s  += __shfl_xor_sync(0xffffffffu, s,  o);
            ss += __shfl_xor_sync(0xffffffffu, ss, o);
        }
        if (l == 0) {
            float mu = s * (1.f / DIMC);
            sm[0]  = mu;
            sm2[0] = rsqrtf(ss * (1.f / DIMC) - mu * mu + LN_EPS);
        }
    }
    __syncthreads();
    const float mu = sm[0], rstd = sm2[0];
    float* orow = out + (size_t)row * DIMC;
    orow[t]       = tf32r((v0 - mu) * rstd * g[t]       + b[t]);
    orow[t + 256] = tf32r((v1 - mu) * rstd * g[t + 256] + b[t + 256]);
    orow[t + 512] = tf32r((v2 - mu) * rstd * g[t + 512] + b[t + 512]);
}

// ---------------- TF32 tensor-core GEMM: C = act(A@B + bias) [+ res] ------------------
// Inputs A,B are PRE-ROUNDED to tf32 grid -> raw-bit fragments, no cvt in inner loop.
#define AS_STRIDE 20
#define BS_STRIDE 136

__global__ __launch_bounds__(256, 2) void gemm_tf32(
    const float* __restrict__ A, const float* __restrict__ B,
    const float* __restrict__ bias, const float* __restrict__ res,
    float* __restrict__ C, int M, int N, int K, int do_gelu, int rnd)
{
    __shared__ alignas(16) float As[2][128 * AS_STRIDE];  // [m][k]
    __shared__ alignas(16) float Bs[2][16 * BS_STRIDE];   // [k][n]

    const int bx = blockIdx.x * 128;
    const int by = blockIdx.y * 128;
    const int tid = threadIdx.x;
    const int wid = tid >> 5;
    const int lane = tid & 31;
    const int g  = lane >> 2;
    const int tg = lane & 3;

    const int wm = (wid & 1) * 64;
    const int wn = (wid >> 1) * 32;

    const int a_row = tid >> 2;
    const int a_kq  = (tid & 3) * 4;
    const int b_k   = tid >> 5;
    const int b_n   = (tid & 31) * 4;

    const float* Ag1 = A + (size_t)(by + a_row)      * K + a_kq;
    const float* Ag2 = A + (size_t)(by + a_row + 64) * K + a_kq;
    const float* Bg1 = B + (size_t)b_k       * N + bx + b_n;
    const float* Bg2 = B + (size_t)(b_k + 8) * N + bx + b_n;

    float acc[4][4][4];
    #pragma unroll
    for (int mt = 0; mt < 4; mt++)
        #pragma unroll
        for (int nt = 0; nt < 4; nt++)
            #pragma unroll
            for (int r = 0; r < 4; r++) acc[mt][nt][r] = 0.f;

    const int KT = K / 16;

    {
        cp_async16(&As[0][a_row * AS_STRIDE + a_kq],        Ag1);
        cp_async16(&As[0][(a_row + 64) * AS_STRIDE + a_kq], Ag2);
        cp_async16(&Bs[0][b_k * BS_STRIDE + b_n],           Bg1);
        cp_async16(&Bs[0][(b_k + 8) * BS_STRIDE + b_n],     Bg2);
        asm volatile("cp.async.commit_group;");
    }

    for (int kt = 0; kt < KT; kt++) {
        const int s = kt & 1;
        if (kt + 1 < KT) {
            const int ns = s ^ 1;
            const int k0 = (kt + 1) * 16;
            cp_async16(&As[ns][a_row * AS_STRIDE + a_kq],        Ag1 + k0);
            cp_async16(&As[ns][(a_row + 64) * AS_STRIDE + a_kq], Ag2 + k0);
            cp_async16(&Bs[ns][b_k * BS_STRIDE + b_n],           Bg1 + (size_t)k0 * N);
            cp_async16(&Bs[ns][(b_k + 8) * BS_STRIDE + b_n],     Bg2 + (size_t)k0 * N);
            asm volatile("cp.async.commit_group;");
            asm volatile("cp.async.wait_group 1;");
        } else {
            asm volatile("cp.async.wait_group 0;");
        }
        __syncthreads();

        const float* as = As[s];
        const float* bs = Bs[s];
        #pragma unroll
        for (int kk = 0; kk < 16; kk += 8) {
            uint32_t af[4][4];
            #pragma unroll
            for (int mt = 0; mt < 4; mt++) {
                const int m0 = wm + mt * 16 + g;
                af[mt][0] = __float_as_uint(as[m0 * AS_STRIDE + kk + tg]);
                af[mt][1] = __float_as_uint(as[(m0 + 8) * AS_STRIDE + kk + tg]);
                af[mt][2] = __float_as_uint(as[m0 * AS_STRIDE + kk + tg + 4]);
                af[mt][3] = __float_as_uint(as[(m0 + 8) * AS_STRIDE + kk + tg + 4]);
            }
            uint32_t bf[4][2];
            #pragma unroll
            for (int nt = 0; nt < 4; nt++) {
                const int n0 = wn + nt * 8 + g;
                bf[nt][0] = __float_as_uint(bs[(kk + tg) * BS_STRIDE + n0]);
                bf[nt][1] = __float_as_uint(bs[(kk + tg + 4) * BS_STRIDE + n0]);
            }
            #pragma unroll
            for (int mt = 0; mt < 4; mt++)
                #pragma unroll
                for (int nt = 0; nt < 4; nt++)
                    mma_m16n8k8(acc[mt][nt], af[mt], bf[nt]);
        }
        __syncthreads();
    }

    #pragma unroll
    for (int mt = 0; mt < 4; mt++) {
        const int r0 = by + wm + mt * 16 + g;
        #pragma unroll
        for (int nt = 0; nt < 4; nt++) {
            const int c0 = bx + wn + nt * 8 + tg * 2;
            const float b0 = bias[c0], b1 = bias[c0 + 1];
            float v00 = acc[mt][nt][0] + b0;
            float v01 = acc[mt][nt][1] + b1;
            float v10 = acc[mt][nt][2] + b0;
            float v11 = acc[mt][nt][3] + b1;
            if (do_gelu) {
                v00 = 0.5f * v00 * (1.0f + erff(v00 * 0.70710678118654752f));
                v01 = 0.5f * v01 * (1.0f + erff(v01 * 0.70710678118654752f));
                v10 = 0.5f * v10 * (1.0f + erff(v10 * 0.70710678118654752f));
                v11 = 0.5f * v11 * (1.0f + erff(v11 * 0.70710678118654752f));
            }
            if (res) {
                const float2 r01 = *(const float2*)&res[(size_t)r0 * N + c0];
                const float2 r11 = *(const float2*)&res[(size_t)(r0 + 8) * N + c0];
                v00 += r01.x; v01 += r01.y;
                v10 += r11.x; v11 += r11.y;
            }
            if (rnd) {
                v00 = tf32r(v00); v01 = tf32r(v01);
                v10 = tf32r(v10); v11 = tf32r(v11);
            }
            *(float2*)&C[(size_t)r0 * N + c0]       = make_float2(v00, v01);
            *(float2*)&C[(size_t)(r0 + 8) * N + c0] = make_float2(v10, v11);
        }
    }
}

// ---------------- TF32 tensor-core flash attention ------------------------------------
// qkv: [NTOK][2304]; q at col h*64, k at 768+h*64, v at 1536+h*64 (all tf32-rounded).
// Block: 128 thr (4 warps), 64 q-rows of one (b,h); warp w handles rows w*16..w*16+15.
// Smem: Ks doubles as the P staging buffer after the S-phase (K tile is dead then).
#define KS_STRIDE 68
#define VS_STRIDE 72

__global__ __launch_bounds__(128) void attn_tc(
    const float* __restrict__ qkv, float* __restrict__ ctx)
{
    const int qt = blockIdx.x, h = blockIdx.y, b = blockIdx.z;
    const int tid = threadIdx.x, w = tid >> 5, lane = tid & 31;
    const int g = lane >> 2, tg = lane & 3;

    __shared__ float Ks[64][KS_STRIDE];   // K tile, then P tile
    __shared__ float Vs[64][VS_STRIDE];

    const int qrow0 = b * SEQ + qt * 64 + w * 16;
    const float* qbase = qkv + (size_t)qrow0 * QKVN + h * HDIM;

    // Q fragments, scaled by 1/8 (exact power of two -> stays on tf32 grid)
    uint32_t af[8][4];
    #pragma unroll
    for (int c = 0; c < 8; c++) {
        af[c][0] = __float_as_uint(0.125f * qbase[(size_t)g       * QKVN + c * 8 + tg]);
        af[c][1] = __float_as_uint(0.125f * qbase[(size_t)(g + 8) * QKVN + c * 8 + tg]);
        af[c][2] = __float_as_uint(0.125f * qbase[(size_t)g       * QKVN + c * 8 + tg + 4]);
        af[c][3] = __float_as_uint(0.125f * qbase[(size_t)(g + 8) * QKVN + c * 8 + tg + 4]);
    }

    float o[8][4];
    #pragma unroll
    for (int nt = 0; nt < 8; nt++)
        #pragma unroll
        for (int r = 0; r < 4; r++) o[nt][r] = 0.f;
    float m0 = -1e30f, m1 = -1e30f, l0 = 0.f, l1 = 0.f;

    for (int kt = 0; kt < SEQ / 64; kt++) {
        const float* kb = qkv + (size_t)(b * SEQ + kt * 64) * QKVN + DIMC + h * HDIM;
        const float* vb = kb + DIMC;
        #pragma unroll
        for (int it = 0; it < 8; it++) {
            int e4  = it * 128 + tid;       // 0..1023
            int row = e4 >> 4;
            int d4  = (e4 & 15) * 4;
            *(float4*)&Ks[row][d4] = *(const float4*)(kb + (size_t)row * QKVN + d4);
            *(float4*)&Vs[row][d4] = *(const float4*)(vb + (size_t)row * QKVN + d4);
        }
        __syncthreads();

        // S = (Q*scale) @ K^T  : 64 mmas
        float s[8][4];
        #pragma unroll
        for (int nt = 0; nt < 8; nt++)
            #pragma unroll
            for (int r = 0; r < 4; r++) s[nt][r] = 0.f;
        #pragma unroll
        for (int c = 0; c < 8; c++) {
            #pragma unroll
            for (int nt = 0; nt < 8; nt++) {
                uint32_t bf[2];
                bf[0] = __float_as_uint(Ks[nt * 8 + g][c * 8 + tg]);
                bf[1] = __float_as_uint(Ks[nt * 8 + g][c * 8 + tg + 4]);
                mma_m16n8k8(s[nt], af[c], bf);
            }
        }

        // online softmax (rows g and g+8; stats reduced across the quad)
        float tm0 = -1e30f, tm1 = -1e30f;
        #pragma unroll
        for (int nt = 0; nt < 8; nt++) {
            tm0 = fmaxf(tm0, fmaxf(s[nt][0], s[nt][1]));
            tm1 = fmaxf(tm1, fmaxf(s[nt][2], s[nt][3]));
        }
        tm0 = fmaxf(tm0, __shfl_xor_sync(0xffffffffu, tm0, 1));
        tm0 = fmaxf(tm0, __shfl_xor_sync(0xffffffffu, tm0, 2));
        tm1 = fmaxf(tm1, __shfl_xor_sync(0xffffffffu, tm1, 1));
        tm1 = fmaxf(tm1, __shfl_xor_sync(0xffffffffu, tm1, 2));
        const float mn0 = fmaxf(m0, tm0), mn1 = fmaxf(m1, tm1);
        const float a0 = __expf(m0 - mn0), a1 = __expf(m1 - mn1);
        m0 = mn0; m1 = mn1;

        float rs0 = 0.f, rs1 = 0.f;
        #pragma unroll
        for (int nt = 0; nt < 8; nt++) {
            s[nt][0] = __expf(s[nt][0] - m0);
            s[nt][1] = __expf(s[nt][1] - m0);
            s[nt][2] = __expf(s[nt][2] - m1);
            s[nt][3] = __expf(s[nt][3] - m1);
            rs0 += s[nt][0] + s[nt][1];
            rs1 += s[nt][2] + s[nt][3];
        }
        rs0 += __shfl_xor_sync(0xffffffffu, rs0, 1);
        rs0 += __shfl_xor_sync(0xffffffffu, rs0, 2);
        rs1 += __shfl_xor_sync(0xffffffffu, rs1, 1);
        rs1 += __shfl_xor_sync(0xffffffffu, rs1, 2);
        l0 = l0 * a0 + rs0;
        l1 = l1 * a1 + rs1;

        #pragma unroll
        for (int nt = 0; nt < 8; nt++) {
            o[nt][0] *= a0; o[nt][1] *= a0;
            o[nt][2] *= a1; o[nt][3] *= a1;
        }

        // all warps must finish reading K tile before it is overwritten by P
        __syncthreads();

        // P -> Ks rows [w*16, w*16+16) (tf32-rounded); each warp touches only its slice
        #pragma unroll
        for (int nt = 0; nt < 8; nt++) {
            *(float2*)&Ks[w * 16 + g][nt * 8 + 2 * tg]     = make_float2(tf32r(s[nt][0]), tf32r(s[nt][1]));
            *(float2*)&Ks[w * 16 + g + 8][nt * 8 + 2 * tg] = make_float2(tf32r(s[nt][2]), tf32r(s[nt][3]));
        }
        __syncwarp();

        // O += P @ V : 64 mmas (P A-fragments read back from own warp's Ks rows)
        #pragma unroll
        for (int c = 0; c < 8; c++) {
            uint32_t pa[4];
            pa[0] = __float_as_uint(Ks[w * 16 + g][c * 8 + tg]);
            pa[1] = __float_as_uint(Ks[w * 16 + g + 8][c * 8 + tg]);
            pa[2] = __float_as_uint(Ks[w * 16 + g][c * 8 + tg + 4]);
            pa[3] = __float_as_uint(Ks[w * 16 + g + 8][c * 8 + tg + 4]);
            #pragma unroll
            for (int nt = 0; nt < 8; nt++) {
                uint32_t vbf[2];
                vbf[0] = __float_as_uint(Vs[c * 8 + tg][nt * 8 + g]);
                vbf[1] = __float_as_uint(Vs[c * 8 + tg + 4][nt * 8 + g]);
                mma_m16n8k8(o[nt], pa, vbf);
            }
        }
        __syncthreads();
    }

    const float inv0 = 1.f / l0, inv1 = 1.f / l1;
    float* c0p = ctx + (size_t)(qrow0 + g)     * DIMC + h * HDIM;
    float* c1p = ctx + (size_t)(qrow0 + g + 8) * DIMC + h * HDIM;
    #pragma unroll
    for (int nt = 0; nt < 8; nt++) {
        *(float2*)&c0p[nt * 8 + 2 * tg] = make_float2(tf32r(o[nt][0] * inv0), tf32r(o[nt][1] * inv0));
        *(float2*)&c1p[nt * 8 + 2 * tg] = make_float2(tf32r(o[nt][2] * inv1), tf32r(o[nt][3] * inv1));
    }
}

// ---------------- launch ----------------
extern "C" void kernel_launch(void* const* d_in, const int* in_sizes, int n_in,
                              void* d_out, int out_size)
{
    const float* x    = (const float*)d_in[0];
    const float* ln1g = (const float*)d_in[1];
    const float* ln1b = (const float*)d_in[2];
    const float* Wq   = (const float*)d_in[3];
    const float* bq   = (const float*)d_in[4];
    const float* Wk   = (const float*)d_in[5];
    const float* bk   = (const float*)d_in[6];
    const float* Wv   = (const float*)d_in[7];
    const float* bv   = (const float*)d_in[8];
    const float* Wo   = (const float*)d_in[9];
    const float* bo   = (const float*)d_in[10];
    const float* ln2g = (const float*)d_in[11];
    const float* ln2b = (const float*)d_in[12];
    const float* W1   = (const float*)d_in[13];
    const float* b1   = (const float*)d_in[14];
    const float* W2   = (const float*)d_in[15];
    const float* b2   = (const float*)d_in[16];
    float* out = (float*)d_out;

    float *h, *qkv, *ctx, *x1, *h2, *ffn;
    float *wqkv, *bqkv, *wo, *w1, *w2;
    cudaGetSymbolAddress((void**)&h,    g_h);
    cudaGetSymbolAddress((void**)&qkv,  g_qkv);
    cudaGetSymbolAddress((void**)&ctx,  g_ctx);
    cudaGetSymbolAddress((void**)&x1,   g_x1);
    cudaGetSymbolAddress((void**)&h2,   g_h2);
    cudaGetSymbolAddress((void**)&ffn,  g_ffn);
    cudaGetSymbolAddress((void**)&wqkv, g_wqkv);
    cudaGetSymbolAddress((void**)&bqkv, g_bqkv);
    cudaGetSymbolAddress((void**)&wo,   g_wo);
    cudaGetSymbolAddress((void**)&w1,   g_w1);
    cudaGetSymbolAddress((void**)&w2,   g_w2);

    const dim3 blk(256);

    // weight prep (rounded to tf32 grid once per launch)
    pack_qkv_w<<<(DIMC * QKVN + 255) / 256, blk>>>(Wq, Wk, Wv, wqkv);
    pack_qkv_b<<<(QKVN + 255) / 256, blk>>>(bq, bk, bv, bqkv);
    round_mat<<<(DIMC * DIMC + 255) / 256, blk>>>(Wo, wo, DIMC * DIMC);
    round_mat<<<(DIMC * HIDDENC + 255) / 256, blk>>>(W1, w1, DIMC * HIDDENC);
    round_mat<<<(HIDDENC * DIMC + 255) / 256, blk>>>(W2, w2, HIDDENC * DIMC);

    const dim3 gqkv(QKVN / 128, NTOK / 128);     // 18 x 128
    const dim3 gd(DIMC / 128, NTOK / 128);       // 6 x 128
    const dim3 gh(HIDDENC / 128, NTOK / 128);    // 24 x 128

    // 1) LN1 (rounded out)
    ln_kernel<<<NTOK, blk>>>(x, ln1g, ln1b, h);
    // 2) fused QKV projection (rounded out)
    gemm_tf32<<<gqkv, blk>>>(h, wqkv, bqkv, nullptr, qkv, NTOK, QKVN, DIMC, 0, 1);
    // 3) tensor-core flash attention (rounded out)
    attn_tc<<<dim3(SEQ / 64, HEADSC, BATCH), 128>>>(qkv, ctx);
    // 4) x1 = x + ctx@Wo + bo (full fp32 out)
    gemm_tf32<<<gd, blk>>>(ctx, wo, bo, x, x1, NTOK, DIMC, DIMC, 0, 0);
    // 5) LN2 (rounded out)
    ln_kernel<<<NTOK, blk>>>(x1, ln2g, ln2b, h2);
    // 6) FFN up + exact GELU (rounded out)
    gemm_tf32<<<gh, blk>>>(h2, w1, b1, nullptr, ffn, NTOK, HIDDENC, DIMC, 1, 1);
    // 7) out = x1 + ffn@W2 + b2 (full fp32 out)
    gemm_tf32<<<gd, blk>>>(ffn, w2, b2, x1, out, NTOK, DIMC, HIDDENC, 0, 0);
}

// round 7
// speedup vs baseline: 3.9441x; 1.0363x over previous
#include <cuda_runtime.h>
#include <math.h>
#include <stdint.h>

#define DIMC    768
#define HIDDENC 3072
#define SEQ     1024
#define BATCH   16
#define NTOK    (BATCH*SEQ)   // 16384
#define HEADSC  12
#define HDIM    64
#define QKVN    (3*DIMC)      // 2304
#define LN_EPS  1e-5f

// ---------------- scratch (static device arrays; no allocation allowed) ----------------
__device__ float g_h   [NTOK*DIMC];
__device__ float g_qkv [NTOK*QKVN];
__device__ float g_ctx [NTOK*DIMC];
__device__ float g_x1  [NTOK*DIMC];
__device__ float g_h2  [NTOK*DIMC];
__device__ float g_ffn [NTOK*HIDDENC];
// pre-rounded (tf32) weights, [K][N] row-major (mma.sync row.col layout)
__device__ float g_wqkv[DIMC*QKVN];
__device__ float g_bqkv[QKVN];
__device__ float g_wo  [DIMC*DIMC];
__device__ float g_w1  [DIMC*HIDDENC];
__device__ float g_w2  [HIDDENC*DIMC];

// ---------------- helpers ----------------
__device__ __forceinline__ float tf32r(float x) {
    uint32_t u;
    asm("cvt.rna.tf32.f32 %0, %1;" : "=r"(u) : "f"(x));
    return __uint_as_float(u);
}

__device__ __forceinline__ void mma_m16n8k8(float d[4], const uint32_t a[4], const uint32_t b[2]) {
    asm volatile(
        "mma.sync.aligned.m16n8k8.row.col.f32.tf32.tf32.f32 "
        "{%0,%1,%2,%3}, {%4,%5,%6,%7}, {%8,%9}, {%0,%1,%2,%3};"
        : "+f"(d[0]), "+f"(d[1]), "+f"(d[2]), "+f"(d[3])
        : "r"(a[0]), "r"(a[1]), "r"(a[2]), "r"(a[3]), "r"(b[0]), "r"(b[1]));
}

__device__ __forceinline__ void cp_async16(void* smem, const void* gmem) {
    uint32_t s = (uint32_t)__cvta_generic_to_shared(smem);
    asm volatile("cp.async.cg.shared.global [%0], [%1], 16;" :: "r"(s), "l"(gmem));
}

// ---------------- weight prep (per-launch; cheap, graph-capturable) -------------------
__global__ __launch_bounds__(256) void pack_qkv_w(
    const float* __restrict__ Wq, const float* __restrict__ Wk,
    const float* __restrict__ Wv, float* __restrict__ out)
{
    int idx = blockIdx.x * 256 + threadIdx.x;
    if (idx >= DIMC * QKVN) return;
    int k = idx / QKVN, j = idx % QKVN;
    float v = (j < DIMC) ? Wq[k * DIMC + j]
            : (j < 2 * DIMC) ? Wk[k * DIMC + j - DIMC]
            : Wv[k * DIMC + j - 2 * DIMC];
    out[idx] = tf32r(v);
}

__global__ void pack_qkv_b(const float* __restrict__ bq, const float* __restrict__ bk,
                           const float* __restrict__ bv, float* __restrict__ out)
{
    int j = blockIdx.x * 256 + threadIdx.x;
    if (j >= QKVN) return;
    out[j] = (j < DIMC) ? bq[j] : (j < 2 * DIMC) ? bk[j - DIMC] : bv[j - 2 * DIMC];
}

__global__ __launch_bounds__(256) void round_mat(const float* __restrict__ in,
                                                 float* __restrict__ out, int n)
{
    int i = blockIdx.x * 256 + threadIdx.x;
    if (i < n) out[i] = tf32r(in[i]);
}

// ---------------- LayerNorm (tf32-rounded output; feeds GEMM A only) ------------------
__global__ __launch_bounds__(256) void ln_kernel(
    const float* __restrict__ x, const float* __restrict__ g,
    const float* __restrict__ b, float* __restrict__ out)
{
    const int row = blockIdx.x;
    const int t = threadIdx.x;
    const float* xr = x + (size_t)row * DIMC;
    float v0 = xr[t], v1 = xr[t + 256], v2 = xr[t + 512];
    float s  = v0 + v1 + v2;
    float ss = v0*v0 + v1*v1 + v2*v2;
    #pragma unroll
    for (int o = 16; o; o >>= 1) {
        s  += __shfl_xor_sync(0xffffffffu, s,  o);
        ss += __shfl_xor_sync(0xffffffffu, ss, o);
    }
    __shared__ float sm[8], sm2[8];
    const int w = t >> 5, l = t & 31;
    if (l == 0) { sm[w] = s; sm2[w] = ss; }
    __syncthreads();
    if (w == 0) {
        s  = (l < 8) ? sm[l]  : 0.f;
        ss = (l < 8) ? sm2[l] : 0.f;
        #pragma unroll
        for (int o = 4; o; o >>= 1) {
            s  += __shfl_xor_sync(0xffffffffu, s,  o);
            ss += __shfl_xor_sync(0xffffffffu, ss, o);
        }
        if (l == 0) {
            float mu = s * (1.f / DIMC);
            sm[0]  = mu;
            sm2[0] = rsqrtf(ss * (1.f / DIMC) - mu * mu + LN_EPS);
        }
    }
    __syncthreads();
    const float mu = sm[0], rstd = sm2[0];
    float* orow = out + (size_t)row * DIMC;
    orow[t]       = tf32r((v0 - mu) * rstd * g[t]       + b[t]);
    orow[t + 256] = tf32r((v1 - mu) * rstd * g[t + 256] + b[t + 256]);
    orow[t + 512] = tf32r((v2 - mu) * rstd * g[t + 512] + b[t + 512]);
}

// ---------------- TF32 tensor-core GEMM: C = act(A@B + bias) [+ res] ------------------
// A: [M,K] row-major, B: [K,N] row-major (both tf32-pre-rounded).
// Block tile 128x128x16, 128 threads (4 warps, 2x2), warp tile 64x64.
// Per kk-step: 32 LDS.32 feed 32 mma.sync (ratio 1.0 vs 1.5 of the 8-warp version).
#define AS_STRIDE 20    // 16 k-floats + 4 pad  -> A-fragment LDS conflict-free
#define BS_STRIDE 136   // 128 n-floats + 8 pad -> B-fragment LDS conflict-free

__global__ __launch_bounds__(128) void gemm_tf32(
    const float* __restrict__ A, const float* __restrict__ B,
    const float* __restrict__ bias, const float* __restrict__ res,
    float* __restrict__ C, int M, int N, int K, int do_gelu, int rnd)
{
    __shared__ alignas(16) float As[2][128 * AS_STRIDE];  // [m][k]
    __shared__ alignas(16) float Bs[2][16 * BS_STRIDE];   // [k][n]

    const int bx = blockIdx.x * 128;
    const int by = blockIdx.y * 128;
    const int tid = threadIdx.x;
    const int wid = tid >> 5;
    const int lane = tid & 31;
    const int g  = lane >> 2;   // 0..7
    const int tg = lane & 3;    // 0..3

    const int wm = (wid & 1) * 64;   // warp row offset
    const int wn = (wid >> 1) * 64;  // warp col offset

    // producer mapping (128 threads, 4 iterations each for A and B)
    const int ar = tid >> 2;           // 0..31 (+32i)
    const int ac = (tid & 3) * 4;      // 0,4,8,12
    const int bk = tid >> 5;           // 0..3  (+4i)
    const int bn = (tid & 31) * 4;     // 0..124

    float acc[4][8][4];
    #pragma unroll
    for (int mt = 0; mt < 4; mt++)
        #pragma unroll
        for (int nt = 0; nt < 8; nt++)
            #pragma unroll
            for (int r = 0; r < 4; r++) acc[mt][nt][r] = 0.f;

    const int KT = K / 16;

    // prologue: stage 0
    #pragma unroll
    for (int i = 0; i < 4; i++) {
        cp_async16(&As[0][(ar + 32 * i) * AS_STRIDE + ac],
                   A + (size_t)(by + ar + 32 * i) * K + ac);
        cp_async16(&Bs[0][(bk + 4 * i) * BS_STRIDE + bn],
                   B + (size_t)(bk + 4 * i) * N + bx + bn);
    }
    asm volatile("cp.async.commit_group;");

    for (int kt = 0; kt < KT; kt++) {
        const int s = kt & 1;
        if (kt + 1 < KT) {
            const int ns = s ^ 1;
            const int k0 = (kt + 1) * 16;
            #pragma unroll
            for (int i = 0; i < 4; i++) {
                cp_async16(&As[ns][(ar + 32 * i) * AS_STRIDE + ac],
                           A + (size_t)(by + ar + 32 * i) * K + k0 + ac);
                cp_async16(&Bs[ns][(bk + 4 * i) * BS_STRIDE + bn],
                           B + (size_t)(k0 + bk + 4 * i) * N + bx + bn);
            }
            asm volatile("cp.async.commit_group;");
            asm volatile("cp.async.wait_group 1;");
        } else {
            asm volatile("cp.async.wait_group 0;");
        }
        __syncthreads();

        const float* as = As[s];
        const float* bs = Bs[s];
        #pragma unroll
        for (int kk = 0; kk < 16; kk += 8) {
            uint32_t af[4][4];
            #pragma unroll
            for (int mt = 0; mt < 4; mt++) {
                const int m0 = wm + mt * 16 + g;
                af[mt][0] = __float_as_uint(as[m0 * AS_STRIDE + kk + tg]);
                af[mt][1] = __float_as_uint(as[(m0 + 8) * AS_STRIDE + kk + tg]);
                af[mt][2] = __float_as_uint(as[m0 * AS_STRIDE + kk + tg + 4]);
                af[mt][3] = __float_as_uint(as[(m0 + 8) * AS_STRIDE + kk + tg + 4]);
            }
            uint32_t bf[8][2];
            #pragma unroll
            for (int nt = 0; nt < 8; nt++) {
                const int n0 = wn + nt * 8 + g;
                bf[nt][0] = __float_as_uint(bs[(kk + tg) * BS_STRIDE + n0]);
                bf[nt][1] = __float_as_uint(bs[(kk + tg + 4) * BS_STRIDE + n0]);
            }
            #pragma unroll
            for (int mt = 0; mt < 4; mt++)
                #pragma unroll
                for (int nt = 0; nt < 8; nt++)
                    mma_m16n8k8(acc[mt][nt], af[mt], bf[nt]);
        }
        __syncthreads();
    }

    // epilogue: bias (+gelu) (+residual) (+tf32 rounding)
    #pragma unroll
    for (int mt = 0; mt < 4; mt++) {
        const int r0 = by + wm + mt * 16 + g;
        #pragma unroll
        for (int nt = 0; nt < 8; nt++) {
            const int c0 = bx + wn + nt * 8 + tg * 2;
            const float b0 = bias[c0], b1 = bias[c0 + 1];
            float v00 = acc[mt][nt][0] + b0;
            float v01 = acc[mt][nt][1] + b1;
            float v10 = acc[mt][nt][2] + b0;
            float v11 = acc[mt][nt][3] + b1;
            if (do_gelu) {
                v00 = 0.5f * v00 * (1.0f + erff(v00 * 0.70710678118654752f));
                v01 = 0.5f * v01 * (1.0f + erff(v01 * 0.70710678118654752f));
                v10 = 0.5f * v10 * (1.0f + erff(v10 * 0.70710678118654752f));
                v11 = 0.5f * v11 * (1.0f + erff(v11 * 0.70710678118654752f));
            }
            if (res) {
                const float2 r01 = *(const float2*)&res[(size_t)r0 * N + c0];
                const float2 r11 = *(const float2*)&res[(size_t)(r0 + 8) * N + c0];
                v00 += r01.x; v01 += r01.y;
                v10 += r11.x; v11 += r11.y;
            }
            if (rnd) {
                v00 = tf32r(v00); v01 = tf32r(v01);
                v10 = tf32r(v10); v11 = tf32r(v11);
            }
            *(float2*)&C[(size_t)r0 * N + c0]       = make_float2(v00, v01);
            *(float2*)&C[(size_t)(r0 + 8) * N + c0] = make_float2(v10, v11);
        }
    }
}

// ---------------- TF32 tensor-core flash attention (unchanged from R4, passing) -------
#define KS_STRIDE 68
#define VS_STRIDE 72

__global__ __launch_bounds__(128) void attn_tc(
    const float* __restrict__ qkv, float* __restrict__ ctx)
{
    const int qt = blockIdx.x, h = blockIdx.y, b = blockIdx.z;
    const int tid = threadIdx.x, w = tid >> 5, lane = tid & 31;
    const int g = lane >> 2, tg = lane & 3;

    __shared__ float Ks[64][KS_STRIDE];   // K tile, then P tile
    __shared__ float Vs[64][VS_STRIDE];

    const int qrow0 = b * SEQ + qt * 64 + w * 16;
    const float* qbase = qkv + (size_t)qrow0 * QKVN + h * HDIM;

    uint32_t af[8][4];
    #pragma unroll
    for (int c = 0; c < 8; c++) {
        af[c][0] = __float_as_uint(0.125f * qbase[(size_t)g       * QKVN + c * 8 + tg]);
        af[c][1] = __float_as_uint(0.125f * qbase[(size_t)(g + 8) * QKVN + c * 8 + tg]);
        af[c][2] = __float_as_uint(0.125f * qbase[(size_t)g       * QKVN + c * 8 + tg + 4]);
        af[c][3] = __float_as_uint(0.125f * qbase[(size_t)(g + 8) * QKVN + c * 8 + tg + 4]);
    }

    float o[8][4];
    #pragma unroll
    for (int nt = 0; nt < 8; nt++)
        #pragma unroll
        for (int r = 0; r < 4; r++) o[nt][r] = 0.f;
    float m0 = -1e30f, m1 = -1e30f, l0 = 0.f, l1 = 0.f;

    for (int kt = 0; kt < SEQ / 64; kt++) {
        const float* kb = qkv + (size_t)(b * SEQ + kt * 64) * QKVN + DIMC + h * HDIM;
        const float* vb = kb + DIMC;
        #pragma unroll
        for (int it = 0; it < 8; it++) {
            int e4  = it * 128 + tid;
            int row = e4 >> 4;
            int d4  = (e4 & 15) * 4;
            *(float4*)&Ks[row][d4] = *(const float4*)(kb + (size_t)row * QKVN + d4);
            *(float4*)&Vs[row][d4] = *(const float4*)(vb + (size_t)row * QKVN + d4);
        }
        __syncthreads();

        float s[8][4];
        #pragma unroll
        for (int nt = 0; nt < 8; nt++)
            #pragma unroll
            for (int r = 0; r < 4; r++) s[nt][r] = 0.f;
        #pragma unroll
        for (int c = 0; c < 8; c++) {
            #pragma unroll
            for (int nt = 0; nt < 8; nt++) {
                uint32_t bf[2];
                bf[0] = __float_as_uint(Ks[nt * 8 + g][c * 8 + tg]);
                bf[1] = __float_as_uint(Ks[nt * 8 + g][c * 8 + tg + 4]);
                mma_m16n8k8(s[nt], af[c], bf);
            }
        }

        float tm0 = -1e30f, tm1 = -1e30f;
        #pragma unroll
        for (int nt = 0; nt < 8; nt++) {
            tm0 = fmaxf(tm0, fmaxf(s[nt][0], s[nt][1]));
            tm1 = fmaxf(tm1, fmaxf(s[nt][2], s[nt][3]));
        }
        tm0 = fmaxf(tm0, __shfl_xor_sync(0xffffffffu, tm0, 1));
        tm0 = fmaxf(tm0, __shfl_xor_sync(0xffffffffu, tm0, 2));
        tm1 = fmaxf(tm1, __shfl_xor_sync(0xffffffffu, tm1, 1));
        tm1 = fmaxf(tm1, __shfl_xor_sync(0xffffffffu, tm1, 2));
        const float mn0 = fmaxf(m0, tm0), mn1 = fmaxf(m1, tm1);
        const float a0 = __expf(m0 - mn0), a1 = __expf(m1 - mn1);
        m0 = mn0; m1 = mn1;

        float rs0 = 0.f, rs1 = 0.f;
        #pragma unroll
        for (int nt = 0; nt < 8; nt++) {
            s[nt][0] = __expf(s[nt][0] - m0);
            s[nt][1] = __expf(s[nt][1] - m0);
            s[nt][2] = __expf(s[nt][2] - m1);
            s[nt][3] = __expf(s[nt][3] - m1);
            rs0 += s[nt][0] + s[nt][1];
            rs1 += s[nt][2] + s[nt][3];
        }
        rs0 += __shfl_xor_sync(0xffffffffu, rs0, 1);
        rs0 += __shfl_xor_sync(0xffffffffu, rs0, 2);
        rs1 += __shfl_xor_sync(0xffffffffu, rs1, 1);
        rs1 += __shfl_xor_sync(0xffffffffu, rs1, 2);
        l0 = l0 * a0 + rs0;
        l1 = l1 * a1 + rs1;

        #pragma unroll
        for (int nt = 0; nt < 8; nt++) {
            o[nt][0] *= a0; o[nt][1] *= a0;
            o[nt][2] *= a1; o[nt][3] *= a1;
        }

        __syncthreads();

        #pragma unroll
        for (int nt = 0; nt < 8; nt++) {
            *(float2*)&Ks[w * 16 + g][nt * 8 + 2 * tg]     = make_float2(tf32r(s[nt][0]), tf32r(s[nt][1]));
            *(float2*)&Ks[w * 16 + g + 8][nt * 8 + 2 * tg] = make_float2(tf32r(s[nt][2]), tf32r(s[nt][3]));
        }
        __syncwarp();

        #pragma unroll
        for (int c = 0; c < 8; c++) {
            uint32_t pa[4];
            pa[0] = __float_as_uint(Ks[w * 16 + g][c * 8 + tg]);
            pa[1] = __float_as_uint(Ks[w * 16 + g + 8][c * 8 + tg]);
            pa[2] = __float_as_uint(Ks[w * 16 + g][c * 8 + tg + 4]);
            pa[3] = __float_as_uint(Ks[w * 16 + g + 8][c * 8 + tg + 4]);
            #pragma unroll
            for (int nt = 0; nt < 8; nt++) {
                uint32_t vbf[2];
                vbf[0] = __float_as_uint(Vs[c * 8 + tg][nt * 8 + g]);
                vbf[1] = __float_as_uint(Vs[c * 8 + tg + 4][nt * 8 + g]);
                mma_m16n8k8(o[nt], pa, vbf);
            }
        }
        __syncthreads();
    }

    const float inv0 = 1.f / l0, inv1 = 1.f / l1;
    float* c0p = ctx + (size_t)(qrow0 + g)     * DIMC + h * HDIM;
    float* c1p = ctx + (size_t)(qrow0 + g + 8) * DIMC + h * HDIM;
    #pragma unroll
    for (int nt = 0; nt < 8; nt++) {
        *(float2*)&c0p[nt * 8 + 2 * tg] = make_float2(tf32r(o[nt][0] * inv0), tf32r(o[nt][1] * inv0));
        *(float2*)&c1p[nt * 8 + 2 * tg] = make_float2(tf32r(o[nt][2] * inv1), tf32r(o[nt][3] * inv1));
    }
}

// ---------------- launch ----------------
extern "C" void kernel_launch(void* const* d_in, const int* in_sizes, int n_in,
                              void* d_out, int out_size)
{
    const float* x    = (const float*)d_in[0];
    const float* ln1g = (const float*)d_in[1];
    const float* ln1b = (const float*)d_in[2];
    const float* Wq   = (const float*)d_in[3];
    const float* bq   = (const float*)d_in[4];
    const float* Wk   = (const float*)d_in[5];
    const float* bk   = (const float*)d_in[6];
    const float* Wv   = (const float*)d_in[7];
    const float* bv   = (const float*)d_in[8];
    const float* Wo   = (const float*)d_in[9];
    const float* bo   = (const float*)d_in[10];
    const float* ln2g = (const float*)d_in[11];
    const float* ln2b = (const float*)d_in[12];
    const float* W1   = (const float*)d_in[13];
    const float* b1   = (const float*)d_in[14];
    const float* W2   = (const float*)d_in[15];
    const float* b2   = (const float*)d_in[16];
    float* out = (float*)d_out;

    float *h, *qkv, *ctx, *x1, *h2, *ffn;
    float *wqkv, *bqkv, *wo, *w1, *w2;
    cudaGetSymbolAddress((void**)&h,    g_h);
    cudaGetSymbolAddress((void**)&qkv,  g_qkv);
    cudaGetSymbolAddress((void**)&ctx,  g_ctx);
    cudaGetSymbolAddress((void**)&x1,   g_x1);
    cudaGetSymbolAddress((void**)&h2,   g_h2);
    cudaGetSymbolAddress((void**)&ffn,  g_ffn);
    cudaGetSymbolAddress((void**)&wqkv, g_wqkv);
    cudaGetSymbolAddress((void**)&bqkv, g_bqkv);
    cudaGetSymbolAddress((void**)&wo,   g_wo);
    cudaGetSymbolAddress((void**)&w1,   g_w1);
    cudaGetSymbolAddress((void**)&w2,   g_w2);

    const dim3 blk(256);
    const dim3 gblk(128);   // GEMM CTAs are 4 warps now

    // weight prep (rounded to tf32 grid once per launch)
    pack_qkv_w<<<(DIMC * QKVN + 255) / 256, blk>>>(Wq, Wk, Wv, wqkv);
    pack_qkv_b<<<(QKVN + 255) / 256, blk>>>(bq, bk, bv, bqkv);
    round_mat<<<(DIMC * DIMC + 255) / 256, blk>>>(Wo, wo, DIMC * DIMC);
    round_mat<<<(DIMC * HIDDENC + 255) / 256, blk>>>(W1, w1, DIMC * HIDDENC);
    round_mat<<<(HIDDENC * DIMC + 255) / 256, blk>>>(W2, w2, HIDDENC * DIMC);

    const dim3 gqkv(QKVN / 128, NTOK / 128);     // 18 x 128
    const dim3 gd(DIMC / 128, NTOK / 128);       // 6 x 128
    const dim3 gh(HIDDENC / 128, NTOK / 128);    // 24 x 128

    // 1) LN1 (rounded out)
    ln_kernel<<<NTOK, blk>>>(x, ln1g, ln1b, h);
    // 2) fused QKV projection (rounded out)
    gemm_tf32<<<gqkv, gblk>>>(h, wqkv, bqkv, nullptr, qkv, NTOK, QKVN, DIMC, 0, 1);
    // 3) tensor-core flash attention (rounded out)
    attn_tc<<<dim3(SEQ / 64, HEADSC, BATCH), 128>>>(qkv, ctx);
    // 4) x1 = x + ctx@Wo + bo (full fp32 out)
    gemm_tf32<<<gd, gblk>>>(ctx, wo, bo, x, x1, NTOK, DIMC, DIMC, 0, 0);
    // 5) LN2 (rounded out)
    ln_kernel<<<NTOK, blk>>>(x1, ln2g, ln2b, h2);
    // 6) FFN up + exact GELU (rounded out)
    gemm_tf32<<<gh, gblk>>>(h2, w1, b1, nullptr, ffn, NTOK, HIDDENC, DIMC, 1, 1);
    // 7) out = x1 + ffn@W2 + b2 (full fp32 out)
    gemm_tf32<<<gd, gblk>>>(ffn, w2, b2, x1, out, NTOK, DIMC, HIDDENC, 0, 0);
}

// round 8
// speedup vs baseline: 4.1630x; 1.0555x over previous
#include <cuda_runtime.h>
#include <math.h>
#include <stdint.h>

#define DIMC    768
#define HIDDENC 3072
#define SEQ     1024
#define BATCH   16
#define NTOK    (BATCH*SEQ)   // 16384
#define HEADSC  12
#define HDIM    64
#define QKVN    (3*DIMC)      // 2304
#define LN_EPS  1e-5f

// ---------------- scratch (static device arrays; no allocation allowed) ----------------
__device__ float g_h   [NTOK*DIMC];
__device__ float g_qkv [NTOK*QKVN];
__device__ float g_ctx [NTOK*DIMC];
__device__ float g_x1  [NTOK*DIMC];
__device__ float g_h2  [NTOK*DIMC];
__device__ float g_ffn [NTOK*HIDDENC];
// pre-rounded (tf32) weights, [K][N] row-major
__device__ float g_wqkv[DIMC*QKVN];
__device__ float g_bqkv[QKVN];
__device__ float g_wo  [DIMC*DIMC];
__device__ float g_w1  [DIMC*HIDDENC];
__device__ float g_w2  [HIDDENC*DIMC];

// ---------------- helpers ----------------
__device__ __forceinline__ float tf32r(float x) {
    uint32_t u;
    asm("cvt.rna.tf32.f32 %0, %1;" : "=r"(u) : "f"(x));
    return __uint_as_float(u);
}

__device__ __forceinline__ void mma_m16n8k8(float d[4], const uint32_t a[4], const uint32_t b[2]) {
    asm volatile(
        "mma.sync.aligned.m16n8k8.row.col.f32.tf32.tf32.f32 "
        "{%0,%1,%2,%3}, {%4,%5,%6,%7}, {%8,%9}, {%0,%1,%2,%3};"
        : "+f"(d[0]), "+f"(d[1]), "+f"(d[2]), "+f"(d[3])
        : "r"(a[0]), "r"(a[1]), "r"(a[2]), "r"(a[3]), "r"(b[0]), "r"(b[1]));
}

__device__ __forceinline__ void cp_async16(void* smem, const void* gmem) {
    uint32_t s = (uint32_t)__cvta_generic_to_shared(smem);
    asm volatile("cp.async.cg.shared.global [%0], [%1], 16;" :: "r"(s), "l"(gmem));
}

// ---------------- weight prep ----------------------------------------------------------
__global__ __launch_bounds__(256) void pack_qkv_w(
    const float* __restrict__ Wq, const float* __restrict__ Wk,
    const float* __restrict__ Wv, float* __restrict__ out)
{
    int idx = blockIdx.x * 256 + threadIdx.x;
    if (idx >= DIMC * QKVN) return;
    int k = idx / QKVN, j = idx % QKVN;
    float v = (j < DIMC) ? Wq[k * DIMC + j]
            : (j < 2 * DIMC) ? Wk[k * DIMC + j - DIMC]
            : Wv[k * DIMC + j - 2 * DIMC];
    out[idx] = tf32r(v);
}

__global__ void pack_qkv_b(const float* __restrict__ bq, const float* __restrict__ bk,
                           const float* __restrict__ bv, float* __restrict__ out)
{
    int j = blockIdx.x * 256 + threadIdx.x;
    if (j >= QKVN) return;
    out[j] = (j < DIMC) ? bq[j] : (j < 2 * DIMC) ? bk[j - DIMC] : bv[j - 2 * DIMC];
}

__global__ __launch_bounds__(256) void round_mat(const float* __restrict__ in,
                                                 float* __restrict__ out, int n)
{
    int i = blockIdx.x * 256 + threadIdx.x;
    if (i < n) out[i] = tf32r(in[i]);
}

// ---------------- LayerNorm (tf32-rounded output) --------------------------------------
__global__ __launch_bounds__(256) void ln_kernel(
    const float* __restrict__ x, const float* __restrict__ g,
    const float* __restrict__ b, float* __restrict__ out)
{
    const int row = blockIdx.x;
    const int t = threadIdx.x;
    const float* xr = x + (size_t)row * DIMC;
    float v0 = xr[t], v1 = xr[t + 256], v2 = xr[t + 512];
    float s  = v0 + v1 + v2;
    float ss = v0*v0 + v1*v1 + v2*v2;
    #pragma unroll
    for (int o = 16; o; o >>= 1) {
        s  += __shfl_xor_sync(0xffffffffu, s,  o);
        ss += __shfl_xor_sync(0xffffffffu, ss, o);
    }
    __shared__ float sm[8], sm2[8];
    const int w = t >> 5, l = t & 31;
    if (l == 0) { sm[w] = s; sm2[w] = ss; }
    __syncthreads();
    if (w == 0) {
        s  = (l < 8) ? sm[l]  : 0.f;
        ss = (l < 8) ? sm2[l] : 0.f;
        #pragma unroll
        for (int o = 4; o; o >>= 1) {
            s  += __shfl_xor_sync(0xffffffffu, s,  o);
            ss += __shfl_xor_sync(0xffffffffu, ss, o);
        }
        if (l == 0) {
            float mu = s * (1.f / DIMC);
            sm[0]  = mu;
            sm2[0] = rsqrtf(ss * (1.f / DIMC) - mu * mu + LN_EPS);
        }
    }
    __syncthreads();
    const float mu = sm[0], rstd = sm2[0];
    float* orow = out + (size_t)row * DIMC;
    orow[t]       = tf32r((v0 - mu) * rstd * g[t]       + b[t]);
    orow[t + 256] = tf32r((v1 - mu) * rstd * g[t + 256] + b[t + 256]);
    orow[t + 512] = tf32r((v2 - mu) * rstd * g[t + 512] + b[t + 512]);
}

// ---------------- TF32 tensor-core GEMM, K=32 stages, dynamic smem ---------------------
// Block 128x128, 128 threads (4 warps 2x2, warp tile 64x64). K staged 32/iter.
#define AS_STRIDE 36     // 32 k + 4 pad  (fragment banks 4g+tg: conflict-free)
#define BS_STRIDE 136    // 128 n + 8 pad (fragment banks 8tg+g: conflict-free)
#define A_TILE (128*AS_STRIDE)
#define B_TILE (32*BS_STRIDE)
#define GEMM_SMEM ((2*(A_TILE+B_TILE))*4)   // 71680 bytes

__global__ __launch_bounds__(128) void gemm_tf32(
    const float* __restrict__ A, const float* __restrict__ B,
    const float* __restrict__ bias, const float* __restrict__ res,
    float* __restrict__ C, int M, int N, int K, int do_gelu, int rnd)
{
    extern __shared__ float smem[];
    float* const AsBase = smem;                 // stage s at s*A_TILE
    float* const BsBase = smem + 2 * A_TILE;    // stage s at s*B_TILE

    const int bx = blockIdx.x * 128;
    const int by = blockIdx.y * 128;
    const int tid = threadIdx.x;
    const int wid = tid >> 5;
    const int lane = tid & 31;
    const int g  = lane >> 2;
    const int tg = lane & 3;

    const int wm = (wid & 1) * 64;
    const int wn = (wid >> 1) * 64;

    float acc[4][8][4];
    #pragma unroll
    for (int mt = 0; mt < 4; mt++)
        #pragma unroll
        for (int nt = 0; nt < 8; nt++)
            #pragma unroll
            for (int r = 0; r < 4; r++) acc[mt][nt][r] = 0.f;

    const int KT = K / 32;

    // producer: 8 float4 chunks each for A (128x32) and B (32x128)
    auto load_stage = [&](int stage, int k0) {
        float* As = AsBase + stage * A_TILE;
        float* Bs = BsBase + stage * B_TILE;
        #pragma unroll
        for (int i = 0; i < 8; i++) {
            const int idx  = tid + 128 * i;       // 0..1023
            const int arow = idx >> 3, ac4 = (idx & 7) * 4;
            cp_async16(&As[arow * AS_STRIDE + ac4],
                       A + (size_t)(by + arow) * K + k0 + ac4);
            const int brow = idx >> 5, bc4 = (idx & 31) * 4;
            cp_async16(&Bs[brow * BS_STRIDE + bc4],
                       B + (size_t)(k0 + brow) * N + bx + bc4);
        }
        asm volatile("cp.async.commit_group;");
    };

    load_stage(0, 0);

    for (int kt = 0; kt < KT; kt++) {
        const int s = kt & 1;
        if (kt + 1 < KT) {
            load_stage(s ^ 1, (kt + 1) * 32);
            asm volatile("cp.async.wait_group 1;");
        } else {
            asm volatile("cp.async.wait_group 0;");
        }
        __syncthreads();

        const float* as = AsBase + s * A_TILE;
        const float* bs = BsBase + s * B_TILE;
        #pragma unroll
        for (int kk = 0; kk < 32; kk += 8) {
            uint32_t af[4][4];
            #pragma unroll
            for (int mt = 0; mt < 4; mt++) {
                const int m0 = wm + mt * 16 + g;
                af[mt][0] = __float_as_uint(as[m0 * AS_STRIDE + kk + tg]);
                af[mt][1] = __float_as_uint(as[(m0 + 8) * AS_STRIDE + kk + tg]);
                af[mt][2] = __float_as_uint(as[m0 * AS_STRIDE + kk + tg + 4]);
                af[mt][3] = __float_as_uint(as[(m0 + 8) * AS_STRIDE + kk + tg + 4]);
            }
            uint32_t bf[8][2];
            #pragma unroll
            for (int nt = 0; nt < 8; nt++) {
                const int n0 = wn + nt * 8 + g;
                bf[nt][0] = __float_as_uint(bs[(kk + tg) * BS_STRIDE + n0]);
                bf[nt][1] = __float_as_uint(bs[(kk + tg + 4) * BS_STRIDE + n0]);
            }
            #pragma unroll
            for (int mt = 0; mt < 4; mt++)
                #pragma unroll
                for (int nt = 0; nt < 8; nt++)
                    mma_m16n8k8(acc[mt][nt], af[mt], bf[nt]);
        }
        __syncthreads();
    }

    // epilogue
    #pragma unroll
    for (int mt = 0; mt < 4; mt++) {
        const int r0 = by + wm + mt * 16 + g;
        #pragma unroll
        for (int nt = 0; nt < 8; nt++) {
            const int c0 = bx + wn + nt * 8 + tg * 2;
            const float b0 = bias[c0], b1 = bias[c0 + 1];
            float v00 = acc[mt][nt][0] + b0;
            float v01 = acc[mt][nt][1] + b1;
            float v10 = acc[mt][nt][2] + b0;
            float v11 = acc[mt][nt][3] + b1;
            if (do_gelu) {
                v00 = 0.5f * v00 * (1.0f + erff(v00 * 0.70710678118654752f));
                v01 = 0.5f * v01 * (1.0f + erff(v01 * 0.70710678118654752f));
                v10 = 0.5f * v10 * (1.0f + erff(v10 * 0.70710678118654752f));
                v11 = 0.5f * v11 * (1.0f + erff(v11 * 0.70710678118654752f));
            }
            if (res) {
                const float2 r01 = *(const float2*)&res[(size_t)r0 * N + c0];
                const float2 r11 = *(const float2*)&res[(size_t)(r0 + 8) * N + c0];
                v00 += r01.x; v01 += r01.y;
                v10 += r11.x; v11 += r11.y;
            }
            if (rnd) {
                v00 = tf32r(v00); v01 = tf32r(v01);
                v10 = tf32r(v10); v11 = tf32r(v11);
            }
            *(float2*)&C[(size_t)r0 * N + c0]       = make_float2(v00, v01);
            *(float2*)&C[(size_t)(r0 + 8) * N + c0] = make_float2(v10, v11);
        }
    }
}

// ---------------- TF32 tensor-core flash attention: 128 q-rows per block ---------------
// 4 warps; warp w owns q-rows [w*32, w*32+32) = 2 m-tiles. K/V tiles 64 wide.
// PV runs per-m-tile, staging that m-tile's P (16 rows/warp) into Ks rows w*16.
#define KS_STRIDE 68
#define VS_STRIDE 72

__global__ __launch_bounds__(128) void attn_tc(
    const float* __restrict__ qkv, float* __restrict__ ctx)
{
    const int qt = blockIdx.x, h = blockIdx.y, b = blockIdx.z;
    const int tid = threadIdx.x, w = tid >> 5, lane = tid & 31;
    const int g = lane >> 2, tg = lane & 3;

    __shared__ float Ks[64][KS_STRIDE];   // K tile, then per-m-tile P staging
    __shared__ float Vs[64][VS_STRIDE];

    const int qrow0 = b * SEQ + qt * 128 + w * 32;   // warp's first q row
    const float* qbase = qkv + (size_t)qrow0 * QKVN + h * HDIM;

    // Q fragments for 2 m-tiles, scaled by 1/8 (exact, stays on tf32 grid)
    uint32_t af[2][8][4];
    #pragma unroll
    for (int mt = 0; mt < 2; mt++)
        #pragma unroll
        for (int c = 0; c < 8; c++) {
            const int r0 = mt * 16 + g;
            af[mt][c][0] = __float_as_uint(0.125f * qbase[(size_t)r0       * QKVN + c * 8 + tg]);
            af[mt][c][1] = __float_as_uint(0.125f * qbase[(size_t)(r0 + 8) * QKVN + c * 8 + tg]);
            af[mt][c][2] = __float_as_uint(0.125f * qbase[(size_t)r0       * QKVN + c * 8 + tg + 4]);
            af[mt][c][3] = __float_as_uint(0.125f * qbase[(size_t)(r0 + 8) * QKVN + c * 8 + tg + 4]);
        }

    float o[2][8][4];
    #pragma unroll
    for (int mt = 0; mt < 2; mt++)
        #pragma unroll
        for (int nt = 0; nt < 8; nt++)
            #pragma unroll
            for (int r = 0; r < 4; r++) o[mt][nt][r] = 0.f;
    float mst[2][2] = {{-1e30f, -1e30f}, {-1e30f, -1e30f}};
    float lst[2][2] = {{0.f, 0.f}, {0.f, 0.f}};

    for (int kt = 0; kt < SEQ / 64; kt++) {
        const float* kb = qkv + (size_t)(b * SEQ + kt * 64) * QKVN + DIMC + h * HDIM;
        const float* vb = kb + DIMC;
        #pragma unroll
        for (int it = 0; it < 8; it++) {
            int e4  = it * 128 + tid;       // 0..1023
            int row = e4 >> 4;
            int d4  = (e4 & 15) * 4;
            *(float4*)&Ks[row][d4] = *(const float4*)(kb + (size_t)row * QKVN + d4);
            *(float4*)&Vs[row][d4] = *(const float4*)(vb + (size_t)row * QKVN + d4);
        }
        __syncthreads();

        // S = (Q*scale) @ K^T for both m-tiles; K-fragments shared across m-tiles
        float s[2][8][4];
        #pragma unroll
        for (int mt = 0; mt < 2; mt++)
            #pragma unroll
            for (int nt = 0; nt < 8; nt++)
                #pragma unroll
                for (int r = 0; r < 4; r++) s[mt][nt][r] = 0.f;
        #pragma unroll
        for (int c = 0; c < 8; c++) {
            #pragma unroll
            for (int nt = 0; nt < 8; nt++) {
                uint32_t bf[2];
                bf[0] = __float_as_uint(Ks[nt * 8 + g][c * 8 + tg]);
                bf[1] = __float_as_uint(Ks[nt * 8 + g][c * 8 + tg + 4]);
                mma_m16n8k8(s[0][nt], af[0][c], bf);
                mma_m16n8k8(s[1][nt], af[1][c], bf);
            }
        }

        // online softmax per m-tile
        float alpha[2][2];
        #pragma unroll
        for (int mt = 0; mt < 2; mt++) {
            float tm0 = -1e30f, tm1 = -1e30f;
            #pragma unroll
            for (int nt = 0; nt < 8; nt++) {
                tm0 = fmaxf(tm0, fmaxf(s[mt][nt][0], s[mt][nt][1]));
                tm1 = fmaxf(tm1, fmaxf(s[mt][nt][2], s[mt][nt][3]));
            }
            tm0 = fmaxf(tm0, __shfl_xor_sync(0xffffffffu, tm0, 1));
            tm0 = fmaxf(tm0, __shfl_xor_sync(0xffffffffu, tm0, 2));
            tm1 = fmaxf(tm1, __shfl_xor_sync(0xffffffffu, tm1, 1));
            tm1 = fmaxf(tm1, __shfl_xor_sync(0xffffffffu, tm1, 2));
            const float mn0 = fmaxf(mst[mt][0], tm0), mn1 = fmaxf(mst[mt][1], tm1);
            alpha[mt][0] = __expf(mst[mt][0] - mn0);
            alpha[mt][1] = __expf(mst[mt][1] - mn1);
            mst[mt][0] = mn0; mst[mt][1] = mn1;

            float rs0 = 0.f, rs1 = 0.f;
            #pragma unroll
            for (int nt = 0; nt < 8; nt++) {
                s[mt][nt][0] = __expf(s[mt][nt][0] - mn0);
                s[mt][nt][1] = __expf(s[mt][nt][1] - mn0);
                s[mt][nt][2] = __expf(s[mt][nt][2] - mn1);
                s[mt][nt][3] = __expf(s[mt][nt][3] - mn1);
                rs0 += s[mt][nt][0] + s[mt][nt][1];
                rs1 += s[mt][nt][2] + s[mt][nt][3];
            }
            rs0 += __shfl_xor_sync(0xffffffffu, rs0, 1);
            rs0 += __shfl_xor_sync(0xffffffffu, rs0, 2);
            rs1 += __shfl_xor_sync(0xffffffffu, rs1, 1);
            rs1 += __shfl_xor_sync(0xffffffffu, rs1, 2);
            lst[mt][0] = lst[mt][0] * alpha[mt][0] + rs0;
            lst[mt][1] = lst[mt][1] * alpha[mt][1] + rs1;

            #pragma unroll
            for (int nt = 0; nt < 8; nt++) {
                o[mt][nt][0] *= alpha[mt][0]; o[mt][nt][1] *= alpha[mt][0];
                o[mt][nt][2] *= alpha[mt][1]; o[mt][nt][3] *= alpha[mt][1];
            }
        }

        // all warps finished reading K tile before P overwrites it
        __syncthreads();

        #pragma unroll
        for (int mt = 0; mt < 2; mt++) {
            // stage P(mt): warp-private rows [w*16, w*16+16)
            #pragma unroll
            for (int nt = 0; nt < 8; nt++) {
                *(float2*)&Ks[w * 16 + g][nt * 8 + 2 * tg]     = make_float2(tf32r(s[mt][nt][0]), tf32r(s[mt][nt][1]));
                *(float2*)&Ks[w * 16 + g + 8][nt * 8 + 2 * tg] = make_float2(tf32r(s[mt][nt][2]), tf32r(s[mt][nt][3]));
            }
            __syncwarp();

            #pragma unroll
            for (int c = 0; c < 8; c++) {
                uint32_t pa[4];
                pa[0] = __float_as_uint(Ks[w * 16 + g][c * 8 + tg]);
                pa[1] = __float_as_uint(Ks[w * 16 + g + 8][c * 8 + tg]);
                pa[2] = __float_as_uint(Ks[w * 16 + g][c * 8 + tg + 4]);
                pa[3] = __float_as_uint(Ks[w * 16 + g + 8][c * 8 + tg + 4]);
                #pragma unroll
                for (int nt = 0; nt < 8; nt++) {
                    uint32_t vbf[2];
                    vbf[0] = __float_as_uint(Vs[c * 8 + tg][nt * 8 + g]);
                    vbf[1] = __float_as_uint(Vs[c * 8 + tg + 4][nt * 8 + g]);
                    mma_m16n8k8(o[mt][nt], pa, vbf);
                }
            }
            __syncwarp();   // before mt=1 restages the same rows
        }
        __syncthreads();    // before next kt overwrites Ks/Vs
    }

    #pragma unroll
    for (int mt = 0; mt < 2; mt++) {
        const float inv0 = 1.f / lst[mt][0], inv1 = 1.f / lst[mt][1];
        float* c0p = ctx + (size_t)(qrow0 + mt * 16 + g)     * DIMC + h * HDIM;
        float* c1p = ctx + (size_t)(qrow0 + mt * 16 + g + 8) * DIMC + h * HDIM;
        #pragma unroll
        for (int nt = 0; nt < 8; nt++) {
            *(float2*)&c0p[nt * 8 + 2 * tg] = make_float2(tf32r(o[mt][nt][0] * inv0), tf32r(o[mt][nt][1] * inv0));
            *(float2*)&c1p[nt * 8 + 2 * tg] = make_float2(tf32r(o[mt][nt][2] * inv1), tf32r(o[mt][nt][3] * inv1));
        }
    }
}

// ---------------- launch ----------------
extern "C" void kernel_launch(void* const* d_in, const int* in_sizes, int n_in,
                              void* d_out, int out_size)
{
    const float* x    = (const float*)d_in[0];
    const float* ln1g = (const float*)d_in[1];
    const float* ln1b = (const float*)d_in[2];
    const float* Wq   = (const float*)d_in[3];
    const float* bq   = (const float*)d_in[4];
    const float* Wk   = (const float*)d_in[5];
    const float* bk   = (const float*)d_in[6];
    const float* Wv   = (const float*)d_in[7];
    const float* bv   = (const float*)d_in[8];
    const float* Wo   = (const float*)d_in[9];
    const float* bo   = (const float*)d_in[10];
    const float* ln2g = (const float*)d_in[11];
    const float* ln2b = (const float*)d_in[12];
    const float* W1   = (const float*)d_in[13];
    const float* b1   = (const float*)d_in[14];
    const float* W2   = (const float*)d_in[15];
    const float* b2   = (const float*)d_in[16];
    float* out = (float*)d_out;

    float *h, *qkv, *ctx, *x1, *h2, *ffn;
    float *wqkv, *bqkv, *wo, *w1, *w2;
    cudaGetSymbolAddress((void**)&h,    g_h);
    cudaGetSymbolAddress((void**)&qkv,  g_qkv);
    cudaGetSymbolAddress((void**)&ctx,  g_ctx);
    cudaGetSymbolAddress((void**)&x1,   g_x1);
    cudaGetSymbolAddress((void**)&h2,   g_h2);
    cudaGetSymbolAddress((void**)&ffn,  g_ffn);
    cudaGetSymbolAddress((void**)&wqkv, g_wqkv);
    cudaGetSymbolAddress((void**)&bqkv, g_bqkv);
    cudaGetSymbolAddress((void**)&wo,   g_wo);
    cudaGetSymbolAddress((void**)&w1,   g_w1);
    cudaGetSymbolAddress((void**)&w2,   g_w2);

    cudaFuncSetAttribute(gemm_tf32, cudaFuncAttributeMaxDynamicSharedMemorySize, GEMM_SMEM);

    const dim3 blk(256);
    const dim3 gblk(128);

    // weight prep (rounded to tf32 grid once per launch)
    pack_qkv_w<<<(DIMC * QKVN + 255) / 256, blk>>>(Wq, Wk, Wv, wqkv);
    pack_qkv_b<<<(QKVN + 255) / 256, blk>>>(bq, bk, bv, bqkv);
    round_mat<<<(DIMC * DIMC + 255) / 256, blk>>>(Wo, wo, DIMC * DIMC);
    round_mat<<<(DIMC * HIDDENC + 255) / 256, blk>>>(W1, w1, DIMC * HIDDENC);
    round_mat<<<(HIDDENC * DIMC + 255) / 256, blk>>>(W2, w2, HIDDENC * DIMC);

    const dim3 gqkv(QKVN / 128, NTOK / 128);     // 18 x 128
    const dim3 gd(DIMC / 128, NTOK / 128);       // 6 x 128
    const dim3 gh(HIDDENC / 128, NTOK / 128);    // 24 x 128

    // 1) LN1 (rounded out)
    ln_kernel<<<NTOK, blk>>>(x, ln1g, ln1b, h);
    // 2) fused QKV projection (rounded out)
    gemm_tf32<<<gqkv, gblk, GEMM_SMEM>>>(h, wqkv, bqkv, nullptr, qkv, NTOK, QKVN, DIMC, 0, 1);
    // 3) tensor-core flash attention, 128 q-rows/block (rounded out)
    attn_tc<<<dim3(SEQ / 128, HEADSC, BATCH), 128>>>(qkv, ctx);
    // 4) x1 = x + ctx@Wo + bo (full fp32 out)
    gemm_tf32<<<gd, gblk, GEMM_SMEM>>>(ctx, wo, bo, x, x1, NTOK, DIMC, DIMC, 0, 0);
    // 5) LN2 (rounded out)
    ln_kernel<<<NTOK, blk>>>(x1, ln2g, ln2b, h2);
    // 6) FFN up + exact GELU (rounded out)
    gemm_tf32<<<gh, gblk, GEMM_SMEM>>>(h2, w1, b1, nullptr, ffn, NTOK, HIDDENC, DIMC, 1, 1);
    // 7) out = x1 + ffn@W2 + b2 (full fp32 out)
    gemm_tf32<<<gd, gblk, GEMM_SMEM>>>(ffn, w2, b2, x1, out, NTOK, DIMC, HIDDENC, 0, 0);
}